// round 13
// baseline (speedup 1.0000x reference)
#include <cuda_runtime.h>
#include <cuda_bf16.h>
#include <cstdint>

#define S_LEN   2048
#define NB      2
#define DMODEL  1024
#define NHEAD   16
#define DKH     64
#define MROWS   (S_LEN * NB)   // 4096
#define PLANE   (S_LEN * DKH)  // 131072 elems per (b,h) plane

#if defined(__CUDA_ARCH_FEAT_SM103_ALL) || defined(__CUDA_ARCH_FEAT_SM100_ALL)
#define HAS_TCGEN05 1
#else
#define HAS_TCGEN05 0
#endif

// ---- bf16 hi/lo scratch ----------------------------------------------------
__device__ __nv_bfloat16 g_qh[MROWS * DMODEL], g_ql[MROWS * DMODEL];
__device__ __nv_bfloat16 g_kh[MROWS * DMODEL], g_kl[MROWS * DMODEL];
__device__ __nv_bfloat16 g_vh[MROWS * DMODEL], g_vl[MROWS * DMODEL];
__device__ __nv_bfloat16 g_wqh[DMODEL * DMODEL], g_wql[DMODEL * DMODEL];
__device__ __nv_bfloat16 g_wkh[DMODEL * DMODEL], g_wkl[DMODEL * DMODEL];
__device__ __nv_bfloat16 g_wvh[DMODEL * DMODEL], g_wvl[DMODEL * DMODEL];
__device__ __nv_bfloat16 g_woh[DMODEL * DMODEL], g_wol[DMODEL * DMODEL];
// projections: Q/K planar [bh][s][d], V planar transposed [bh][d][s]
__device__ __nv_bfloat16 g_Qh[32 * PLANE], g_Ql[32 * PLANE];
__device__ __nv_bfloat16 g_Kh[32 * PLANE], g_Kl[32 * PLANE];
__device__ __nv_bfloat16 g_Vth[32 * PLANE], g_Vtl[32 * PLANE];
__device__ __nv_bfloat16 g_AOh[MROWS * DMODEL], g_AOl[MROWS * DMODEL];

// ---------------------------------------------------------------------------
__device__ __forceinline__ uint32_t smem_u32(const void* p) {
    uint32_t a;
    asm("{ .reg .u64 t; cvta.to.shared.u64 t, %1; cvt.u32.u64 %0, t; }"
        : "=r"(a) : "l"(p));
    return a;
}
__device__ __forceinline__ uint32_t elect_one() {
    uint32_t p;
    asm volatile("{ .reg .pred p; elect.sync _|p, 0xFFFFFFFF; selp.b32 %0,1,0,p; }"
                 : "=r"(p));
    return p;
}
__device__ __forceinline__ uint32_t bf2_bits(__nv_bfloat162 v) {
    return *reinterpret_cast<uint32_t*>(&v);
}

#define MBAR_INIT(addr, cnt) \
    asm volatile("mbarrier.init.shared.b64 [%0], %1;" :: "r"(addr), "r"(cnt) : "memory")

#define MBAR_WAIT(addr, parity) do {                                          \
    uint32_t _m = (addr); uint32_t _p = (parity); uint32_t _d;                \
    asm volatile("{ .reg .pred p; mbarrier.try_wait.parity.acquire.cta.shared::cta.b64 p, [%1], %2;" \
                 " selp.b32 %0,1,0,p; }" : "=r"(_d) : "r"(_m), "r"(_p) : "memory"); \
    if (!_d) {                                                                \
        asm volatile("{ .reg .pred P1; WL_%=:"                                \
                     " mbarrier.try_wait.parity.acquire.cta.shared::cta.b64 P1, [%0], %1, 0x989680;" \
                     " @P1 bra.uni WD_%=; bra.uni WL_%=; WD_%=: }"            \
                     :: "r"(_m), "r"(_p) : "memory");                         \
    }                                                                         \
} while (0)

#if HAS_TCGEN05
#define TC_ALLOC(smem_addr, ncols) \
    asm volatile("tcgen05.alloc.cta_group::1.sync.aligned.shared::cta.b32 [%0], %1;" \
                 :: "r"(smem_addr), "r"(ncols) : "memory")
#define TC_RELINQ() \
    asm volatile("tcgen05.relinquish_alloc_permit.cta_group::1.sync.aligned;")
#define TC_DEALLOC(tmem, ncols) \
    asm volatile("tcgen05.dealloc.cta_group::1.sync.aligned.b32 %0, %1;" :: "r"(tmem), "r"(ncols))
#define TC_COMMIT(mbar) \
    asm volatile("tcgen05.commit.cta_group::1.mbarrier::arrive::one.shared::cluster.b64 [%0];" \
                 :: "r"(mbar) : "memory")
#define TC_FENCE_AFTER()   asm volatile("tcgen05.fence::after_thread_sync;" ::: "memory")
#define TC_FENCE_BEFORE()  asm volatile("tcgen05.fence::before_thread_sync;" ::: "memory")
#define TC_WAIT_LD()       asm volatile("tcgen05.wait::ld.sync.aligned;" ::: "memory")
#define TC_WAIT_ST()       asm volatile("tcgen05.wait::st.sync.aligned;" ::: "memory")

#define TC_LD_X32(r, tmem_addr) \
    asm volatile( \
        "tcgen05.ld.sync.aligned.32x32b.x32.b32 " \
        "{%0, %1, %2, %3, %4, %5, %6, %7, %8, %9, %10, %11, %12, %13, %14, %15, " \
        " %16, %17, %18, %19, %20, %21, %22, %23, %24, %25, %26, %27, %28, %29, %30, %31}, [%32];" \
        : "=r"((r)[0]),  "=r"((r)[1]),  "=r"((r)[2]),  "=r"((r)[3]), \
          "=r"((r)[4]),  "=r"((r)[5]),  "=r"((r)[6]),  "=r"((r)[7]), \
          "=r"((r)[8]),  "=r"((r)[9]),  "=r"((r)[10]), "=r"((r)[11]), \
          "=r"((r)[12]), "=r"((r)[13]), "=r"((r)[14]), "=r"((r)[15]), \
          "=r"((r)[16]), "=r"((r)[17]), "=r"((r)[18]), "=r"((r)[19]), \
          "=r"((r)[20]), "=r"((r)[21]), "=r"((r)[22]), "=r"((r)[23]), \
          "=r"((r)[24]), "=r"((r)[25]), "=r"((r)[26]), "=r"((r)[27]), \
          "=r"((r)[28]), "=r"((r)[29]), "=r"((r)[30]), "=r"((r)[31]) \
        : "r"(tmem_addr))

#define TC_ST_X16(tmem_addr, r) \
    asm volatile( \
        "tcgen05.st.sync.aligned.32x32b.x16.b32 [%0], " \
        "{%1, %2, %3, %4, %5, %6, %7, %8, %9, %10, %11, %12, %13, %14, %15, %16};" \
        :: "r"(tmem_addr), \
           "r"((r)[0]),  "r"((r)[1]),  "r"((r)[2]),  "r"((r)[3]), \
           "r"((r)[4]),  "r"((r)[5]),  "r"((r)[6]),  "r"((r)[7]), \
           "r"((r)[8]),  "r"((r)[9]),  "r"((r)[10]), "r"((r)[11]), \
           "r"((r)[12]), "r"((r)[13]), "r"((r)[14]), "r"((r)[15]) \
        : "memory")

__device__ __forceinline__ void mma_f16_ss(uint32_t d_tmem, uint64_t a_desc,
                                           uint64_t b_desc, uint32_t idesc,
                                           uint32_t enable) {
    asm volatile(
        "{ .reg .pred p; setp.ne.u32 p, %4, 0;\n\t"
        "tcgen05.mma.cta_group::1.kind::f16 [%0], %1, %2, %3, {%5,%5,%5,%5}, p;\n\t}"
        :: "r"(d_tmem), "l"(a_desc), "l"(b_desc), "r"(idesc), "r"(enable), "r"(0u)
        : "memory");
}
__device__ __forceinline__ void mma_f16_ts(uint32_t d_tmem, uint32_t a_tmem,
                                           uint64_t b_desc, uint32_t idesc,
                                           uint32_t enable) {
    asm volatile(
        "{ .reg .pred p; setp.ne.u32 p, %4, 0;\n\t"
        "tcgen05.mma.cta_group::1.kind::f16 [%0], [%1], %2, %3, {%5,%5,%5,%5}, p;\n\t}"
        :: "r"(d_tmem), "r"(a_tmem), "l"(b_desc), "r"(idesc), "r"(enable), "r"(0u)
        : "memory");
}
#endif // HAS_TCGEN05

#define SWZ(o)   ((uint32_t)(o) ^ ((((uint32_t)(o)) >> 3) & 0x70u))
#define SWZ64(o) ((uint32_t)(o) ^ ((((uint32_t)(o)) >> 3) & 0x30u))

// SW128 K-major smem descriptor: LBO=1, SBO=64
static __device__ __forceinline__ uint64_t make_desc(uint32_t addr) {
    const uint64_t base = (uint64_t(2) << 61) | (uint64_t(1) << 46) |
                          (uint64_t(64) << 32) | (uint64_t(1) << 16);
    return base | ((uint64_t)(addr >> 4) & 0x3FFFu);
}
// SW64 K-major smem descriptor: layout=4, LBO=1, SBO=32
static __device__ __forceinline__ uint64_t make_desc64(uint32_t addr) {
    const uint64_t base = (uint64_t(4) << 61) | (uint64_t(1) << 46) |
                          (uint64_t(32) << 32) | (uint64_t(1) << 16);
    return base | ((uint64_t)(addr >> 4) & 0x3FFFu);
}

// ---------------------------------------------------------------------------
// Fused fp32 -> bf16 hi/lo split for all 7 tensors (one launch)
// ---------------------------------------------------------------------------
__global__ void __launch_bounds__(256)
cvt_all(const float4* s0, const float4* s1, const float4* s2, const float4* s3,
        const float4* s4, const float4* s5, const float4* s6,
        uint2* h0, uint2* h1, uint2* h2, uint2* h3, uint2* h4, uint2* h5, uint2* h6,
        uint2* l0, uint2* l1, uint2* l2, uint2* l3, uint2* l4, uint2* l5, uint2* l6)
{
    const float4* srcs[7] = { s0, s1, s2, s3, s4, s5, s6 };
    uint2* hs[7] = { h0, h1, h2, h3, h4, h5, h6 };
    uint2* ls[7] = { l0, l1, l2, l3, l4, l5, l6 };
    const int which = blockIdx.y;
    const int n4 = (which < 3) ? (MROWS * DMODEL / 4) : (DMODEL * DMODEL / 4);
    const int base = blockIdx.x * 1024 + threadIdx.x;
    if (base >= n4) return;
    const float4* __restrict__ x = srcs[which];
    uint2* __restrict__ h = hs[which];
    uint2* __restrict__ l = ls[which];
#pragma unroll
    for (int t = 0; t < 4; t++) {
        const int i = base + t * 256;
        if (i >= n4) break;
        float4 f = x[i];
        __nv_bfloat162 hh0 = __floats2bfloat162_rn(f.x, f.y);
        __nv_bfloat162 hh1 = __floats2bfloat162_rn(f.z, f.w);
        float2 hf0 = __bfloat1622float2(hh0), hf1 = __bfloat1622float2(hh1);
        __nv_bfloat162 ll0 = __floats2bfloat162_rn(f.x - hf0.x, f.y - hf0.y);
        __nv_bfloat162 ll1 = __floats2bfloat162_rn(f.z - hf1.x, f.w - hf1.y);
        uint2 hv, lv;
        hv.x = bf2_bits(hh0); hv.y = bf2_bits(hh1);
        lv.x = bf2_bits(ll0); lv.y = bf2_bits(ll1);
        h[i] = hv; l[i] = lv;
    }
}

// ---------------------------------------------------------------------------
// GEMM, K-chunk 32, SW64 tiles, one-deep prefetch (round-11 core),
// multi-problem via blockIdx.z, __launch_bounds__(256,3) for 3 CTAs/SM.
// ---------------------------------------------------------------------------
#define GSMEM (1024 + 2 * 32768)

struct GemmProb {
    const __nv_bfloat16 *Ah, *Al, *Bh, *Bl;
    const float* bias;
    float* out32;
    __nv_bfloat16 *outh, *outl;
    int mode;   // 0: fp32 row-major; 1: planar [bh][s][d]; 2: planar [bh][d][s]
};
struct GemmProb3 { GemmProb p[3]; };

__global__ void __launch_bounds__(256, 3)
gemm_tc(GemmProb3 ps)
{
#if HAS_TCGEN05
    extern __shared__ char smc[];
    const uint32_t sb = smem_u32(smc);
    const GemmProb P = ps.p[blockIdx.z];
    const __nv_bfloat16* __restrict__ Ah = P.Ah;
    const __nv_bfloat16* __restrict__ Al = P.Al;
    const __nv_bfloat16* __restrict__ Bh = P.Bh;
    const __nv_bfloat16* __restrict__ Bl = P.Bl;
    const int mode = P.mode;
    const int tid = threadIdx.x;
    const int wid = tid >> 5, lid = tid & 31;
    const int m0 = blockIdx.y * 128;
    const int n0 = blockIdx.x * 128;

    if (tid == 0) { MBAR_INIT(sb + 8, 1); MBAR_INIT(sb + 16, 1); }
    if (wid == 0) { TC_ALLOC(sb, 128); TC_RELINQ(); }
    __syncthreads();
    uint32_t tmem;
    asm("ld.shared.b32 %0, [%1];" : "=r"(tmem) : "r"(sb));

    const uint32_t idesc = (1u << 4) | (1u << 7) | (1u << 10) | (16u << 17) | (8u << 24);

    const __nv_bfloat16* srcp[8];
    uint32_t soff[8];
#pragma unroll
    for (int t = 0; t < 8; t++) {
        const int which = t >> 1;
        const int r = (t & 1) * 256 + tid;
        const int row = r >> 2, g = r & 3;
        const __nv_bfloat16* src =
            (which == 0) ? Ah : (which == 1) ? Al : (which == 2) ? Bh : Bl;
        const int base_mn = (which < 2) ? m0 : n0;
        srcp[t] = src + (size_t)(base_mn + row) * DMODEL + g * 8;
        soff[t] = (uint32_t)which * 8192u + SWZ64(row * 64 + g * 16);
    }

    uint4 rg[8];
#pragma unroll
    for (int t = 0; t < 8; t++) rg[t] = *(const uint4*)srcp[t];

    for (int ch = 0; ch < 32; ch++) {
        const int buf = ch & 1;
        const uint32_t tb = 1024u + (uint32_t)buf * 32768u;
        if (ch >= 2) MBAR_WAIT(sb + 8 + buf * 8, ((ch - 2) >> 1) & 1);

#pragma unroll
        for (int t = 0; t < 8; t++)
            *(uint4*)(smc + tb + soff[t]) = rg[t];
        __syncthreads();

        if (ch < 31) {
            const int koff = (ch + 1) * 32;
#pragma unroll
            for (int t = 0; t < 8; t++)
                rg[t] = *(const uint4*)(srcp[t] + koff);
        }

        if (wid == 0 && elect_one()) {
            asm volatile("fence.proxy.async.shared::cta;" ::: "memory");
            const uint64_t dAh = make_desc64(sb + tb);
            const uint64_t dAl = make_desc64(sb + tb + 8192);
            const uint64_t dBh = make_desc64(sb + tb + 16384);
            const uint64_t dBl = make_desc64(sb + tb + 24576);
#pragma unroll
            for (int ks = 0; ks < 2; ks++)
                mma_f16_ss(tmem, dAh + ks * 2, dBh + ks * 2, idesc,
                           (ch == 0 && ks == 0) ? 0u : 1u);
#pragma unroll
            for (int ks = 0; ks < 2; ks++)
                mma_f16_ss(tmem, dAh + ks * 2, dBl + ks * 2, idesc, 1u);
#pragma unroll
            for (int ks = 0; ks < 2; ks++)
                mma_f16_ss(tmem, dAl + ks * 2, dBh + ks * 2, idesc, 1u);
            TC_COMMIT(sb + 8 + buf * 8);
        }
    }

    MBAR_WAIT(sb + 16, 1);
    TC_FENCE_AFTER();

    if (wid < 4) {
        const int m = m0 + wid * 32 + lid;
        const int s = m >> 1, b = m & 1;
#pragma unroll
        for (int c0 = 0; c0 < 128; c0 += 32) {
            uint32_t r[32];
            TC_LD_X32(r, tmem + c0);
            TC_WAIT_LD();
            if (mode == 0) {
#pragma unroll
                for (int j = 0; j < 32; j += 4) {
                    float4 bv = *(const float4*)&P.bias[n0 + c0 + j];
                    float4 o;
                    o.x = __uint_as_float(r[j + 0]) + bv.x;
                    o.y = __uint_as_float(r[j + 1]) + bv.y;
                    o.z = __uint_as_float(r[j + 2]) + bv.z;
                    o.w = __uint_as_float(r[j + 3]) + bv.w;
                    *(float4*)&P.out32[(size_t)m * DMODEL + n0 + c0 + j] = o;
                }
            } else {
                const int nb = n0 + c0;
                const int h = nb >> 6, d0 = nb & 63;
                const size_t plane = (size_t)(b * NHEAD + h) * PLANE;
                __nv_bfloat16 vh[32], vl[32];
#pragma unroll
                for (int j = 0; j < 32; j++) {
                    float val = __uint_as_float(r[j]) + P.bias[nb + j];
                    vh[j] = __float2bfloat16_rn(val);
                    vl[j] = __float2bfloat16_rn(val - __bfloat162float(vh[j]));
                }
                if (mode == 1) {
                    const size_t base = plane + (size_t)s * 64 + d0;
#pragma unroll
                    for (int j = 0; j < 32; j += 4) {
                        uint2 u;
                        u.x = bf2_bits(__nv_bfloat162(vh[j], vh[j + 1]));
                        u.y = bf2_bits(__nv_bfloat162(vh[j + 2], vh[j + 3]));
                        *(uint2*)&P.outh[base + j] = u;
                        u.x = bf2_bits(__nv_bfloat162(vl[j], vl[j + 1]));
                        u.y = bf2_bits(__nv_bfloat162(vl[j + 2], vl[j + 3]));
                        *(uint2*)&P.outl[base + j] = u;
                    }
                } else {
                    const size_t base = plane + s;
#pragma unroll
                    for (int j = 0; j < 32; j++) {
                        P.outh[base + (size_t)(d0 + j) * S_LEN] = vh[j];
                        P.outl[base + (size_t)(d0 + j) * S_LEN] = vl[j];
                    }
                }
            }
        }
    }
    __syncthreads();
    if (wid == 0) TC_DEALLOC(tmem, 128);

#else  // ---------------- fp32 fallback ------------------------------------
    extern __shared__ char smc[];
    float* As = (float*)smc;
    float* Bs = As + 8 * 128;
    const GemmProb P = ps.p[blockIdx.z];
    const int mode = P.mode;

    const int tid  = threadIdx.x;
    const int m0   = blockIdx.y * 128;
    const int n0   = blockIdx.x * 128;
    const int tx   = tid & 15;
    const int ty   = tid >> 4;
    const int lrow = tid >> 1;
    const int lc   = (tid & 1) * 4;

    float acc[8][8];
#pragma unroll
    for (int i = 0; i < 8; i++)
#pragma unroll
        for (int j = 0; j < 8; j++) acc[i][j] = 0.0f;

    for (int k0 = 0; k0 < DMODEL; k0 += 8) {
        float av[4], bv[4];
#pragma unroll
        for (int j = 0; j < 4; j++) {
            size_t ai = (size_t)(m0 + lrow) * DMODEL + k0 + lc + j;
            size_t bi = (size_t)(n0 + lrow) * DMODEL + k0 + lc + j;
            av[j] = __bfloat162float(P.Ah[ai]) + __bfloat162float(P.Al[ai]);
            bv[j] = __bfloat162float(P.Bh[bi]) + __bfloat162float(P.Bl[bi]);
        }
        __syncthreads();
#pragma unroll
        for (int j = 0; j < 4; j++) {
            As[(lc + j) * 128 + lrow] = av[j];
            Bs[(lc + j) * 128 + lrow] = bv[j];
        }
        __syncthreads();
#pragma unroll
        for (int kk = 0; kk < 8; kk++) {
            float a[8], b[8];
            *(float4*)&a[0] = *(const float4*)&As[kk * 128 + ty * 8];
            *(float4*)&a[4] = *(const float4*)&As[kk * 128 + ty * 8 + 4];
            *(float4*)&b[0] = *(const float4*)&Bs[kk * 128 + tx * 8];
            *(float4*)&b[4] = *(const float4*)&Bs[kk * 128 + tx * 8 + 4];
#pragma unroll
            for (int i = 0; i < 8; i++)
#pragma unroll
                for (int j = 0; j < 8; j++)
                    acc[i][j] = fmaf(a[i], b[j], acc[i][j]);
        }
    }

#pragma unroll
    for (int i = 0; i < 8; i++) {
        const int m = m0 + ty * 8 + i;
        const int s = m >> 1, b = m & 1;
#pragma unroll
        for (int j = 0; j < 8; j++) {
            const int n = n0 + tx * 8 + j;
            const float val = acc[i][j] + P.bias[n];
            if (mode == 0) {
                P.out32[(size_t)m * DMODEL + n] = val;
            } else {
                const int h = n >> 6, d = n & 63;
                const size_t plane = (size_t)(b * NHEAD + h) * PLANE;
                const size_t idx = (mode == 1) ? plane + (size_t)s * 64 + d
                                               : plane + (size_t)d * S_LEN + s;
                __nv_bfloat16 hv = __float2bfloat16_rn(val);
                P.outh[idx] = hv;
                P.outl[idx] = __float2bfloat16_rn(val - __bfloat162float(hv));
            }
        }
    }
#endif
}

// ---------------------------------------------------------------------------
// tcgen05 flash attention (round-11 version, unchanged).
// ---------------------------------------------------------------------------
#define FQH  1024u
#define FQL  17408u
#define FBUF 33792u
#define FSMEM 99328

__global__ void __launch_bounds__(256, 2)
flash_tc()
{
#if HAS_TCGEN05
    extern __shared__ char smc[];
    const uint32_t sb = smem_u32(smc);
    const int tid  = threadIdx.x;
    const int wid  = tid >> 5;
    const int lane = tid & 31;
    const int sub  = wid & 3;
    const int chf  = wid >> 2;
    const int bh   = blockIdx.y;
    const int q0   = blockIdx.x * 128;
    const int bb   = bh >> 4;
    const int hh   = bh & 15;
    const size_t plane = (size_t)bh * PLANE;

    if (tid == 0) { MBAR_INIT(sb + 8, 1); MBAR_INIT(sb + 16, 1); }
    if (wid == 0) { TC_ALLOC(sb, 256); TC_RELINQ(); }
    __syncthreads();
    uint32_t tmem;
    asm("ld.shared.b32 %0, [%1];" : "=r"(tmem) : "r"(sb));

    const uint32_t idesc = (1u << 4) | (1u << 7) | (1u << 10) | (8u << 17) | (8u << 24);
    const uint32_t sub_off = (uint32_t)sub << 21;

#pragma unroll
    for (int t = 0; t < 4; t++) {
        const int idx = t * 256 + tid;
        const int row = idx >> 3, g = idx & 7;
        const size_t off = plane + (size_t)(q0 + row) * 64 + g * 8;
        *(uint4*)(smc + FQH + SWZ(row * 128 + g * 16)) = *(const uint4*)&g_Qh[off];
        *(uint4*)(smc + FQL + SWZ(row * 128 + g * 16)) = *(const uint4*)&g_Ql[off];
    }
#pragma unroll
    for (int t = 0; t < 8; t++) {
        const int idx = t * 256 + tid;
        const int which = idx >> 9;
        const int r = idx & 511;
        const int row = r >> 3, g = r & 7;
        const size_t off = (which < 2) ? plane + (size_t)row * 64 + g * 8
                                       : plane + (size_t)row * S_LEN + g * 8;
        const __nv_bfloat16* src =
            (which == 0) ? g_Kh : (which == 1) ? g_Kl : (which == 2) ? g_Vth : g_Vtl;
        *(uint4*)(smc + FBUF + (uint32_t)which * 8192u + SWZ(row * 128 + g * 16)) =
            *(const uint4*)&src[off];
    }
    __syncthreads();

    const uint64_t dQh = make_desc(sb + FQH);
    const uint64_t dQl = make_desc(sb + FQL);

    if (wid == 0 && elect_one()) {
        asm volatile("fence.proxy.async.shared::cta;" ::: "memory");
        const uint64_t dKh = make_desc(sb + FBUF);
        const uint64_t dKl = make_desc(sb + FBUF + 8192);
#pragma unroll
        for (int ks = 0; ks < 4; ks++)
            mma_f16_ss(tmem, dQh + ks * 2, dKh + ks * 2, idesc, ks == 0 ? 0u : 1u);
#pragma unroll
        for (int ks = 0; ks < 4; ks++)
            mma_f16_ss(tmem, dQh + ks * 2, dKl + ks * 2, idesc, 1u);
#pragma unroll
        for (int ks = 0; ks < 4; ks++)
            mma_f16_ss(tmem, dQl + ks * 2, dKh + ks * 2, idesc, 1u);
        TC_COMMIT(sb + 8);
    }

    float lrun = 0.0f;

    for (int kt = 0; kt < 32; kt++) {
        const int cur = kt & 1;
        const uint32_t bufc = FBUF + (uint32_t)cur * 32768u;
        const uint32_t bufn = FBUF + (uint32_t)(cur ^ 1) * 32768u;
        const uint32_t sS = tmem + (uint32_t)cur * 64u;

        if (kt < 31) {
            const int k0n = (kt + 1) * 64;
#pragma unroll
            for (int t = 0; t < 4; t++) {
                const int idx = t * 256 + tid;
                const int which = idx >> 9;
                const int r = idx & 511;
                const int row = r >> 3, g = r & 7;
                const size_t koff = plane + (size_t)(k0n + row) * 64 + g * 8;
                const __nv_bfloat16* src = which ? g_Kl : g_Kh;
                *(uint4*)(smc + bufn + (uint32_t)which * 8192u + SWZ(row * 128 + g * 16)) =
                    *(const uint4*)&src[koff];
            }
        }

        MBAR_WAIT(sb + 8, kt & 1);
        TC_FENCE_AFTER();
        float p[32];
        {
            uint32_t r0[32];
            TC_LD_X32(r0, sS + chf * 32);
            TC_WAIT_LD();
#pragma unroll
            for (int j = 0; j < 32; j++) p[j] = __uint_as_float(r0[j]);
        }
        TC_FENCE_BEFORE();

        __syncthreads();
        if (kt < 31 && wid == 0 && elect_one()) {
            TC_FENCE_AFTER();
            asm volatile("fence.proxy.async.shared::cta;" ::: "memory");
            const uint64_t dKh = make_desc(sb + bufn);
            const uint64_t dKl = make_desc(sb + bufn + 8192);
            const uint32_t sN = tmem + (uint32_t)(cur ^ 1) * 64u;
#pragma unroll
            for (int ks = 0; ks < 4; ks++)
                mma_f16_ss(sN, dQh + ks * 2, dKh + ks * 2, idesc, ks == 0 ? 0u : 1u);
#pragma unroll
            for (int ks = 0; ks < 4; ks++)
                mma_f16_ss(sN, dQh + ks * 2, dKl + ks * 2, idesc, 1u);
#pragma unroll
            for (int ks = 0; ks < 4; ks++)
                mma_f16_ss(sN, dQl + ks * 2, dKh + ks * 2, idesc, 1u);
            TC_COMMIT(sb + 8);
        }

        float rs = 0.0f;
#pragma unroll
        for (int j = 0; j < 32; j++) {
            p[j] = __expf(fmaf(p[j], 0.125f, -12.0f));
            rs += p[j];
        }
        lrun += rs;

        if (kt > 0) {
            MBAR_WAIT(sb + 16, (kt - 1) & 1);
            TC_FENCE_AFTER();
        }

        if (kt < 31) {
            const int k0n = (kt + 1) * 64;
#pragma unroll
            for (int t = 0; t < 4; t++) {
                const int idx = t * 256 + tid;
                const int which = idx >> 9;
                const int r = idx & 511;
                const int row = r >> 3, g = r & 7;
                const size_t voff = plane + (size_t)row * S_LEN + k0n + g * 8;
                const __nv_bfloat16* src = which ? g_Vtl : g_Vth;
                *(uint4*)(smc + bufn + 16384u + (uint32_t)which * 8192u + SWZ(row * 128 + g * 16)) =
                    *(const uint4*)&src[voff];
            }
        }

        {
            uint32_t ph[16], pl[16];
#pragma unroll
            for (int j = 0; j < 16; j++) {
                __nv_bfloat162 h = __floats2bfloat162_rn(p[2 * j], p[2 * j + 1]);
                float2 hf = __bfloat1622float2(h);
                __nv_bfloat162 l = __floats2bfloat162_rn(p[2 * j] - hf.x, p[2 * j + 1] - hf.y);
                ph[j] = bf2_bits(h);
                pl[j] = bf2_bits(l);
            }
            TC_ST_X16(tmem + 192 + chf * 16 + sub_off, ph);
            TC_ST_X16(tmem + 224 + chf * 16 + sub_off, pl);
            TC_WAIT_ST();
        }
        TC_FENCE_BEFORE();
        __syncthreads();

        if (wid == 0 && elect_one()) {
            TC_FENCE_AFTER();
            asm volatile("fence.proxy.async.shared::cta;" ::: "memory");
            const uint64_t dVh = make_desc(sb + bufc + 16384);
            const uint64_t dVl = make_desc(sb + bufc + 24576);
#pragma unroll
            for (int ks = 0; ks < 4; ks++)
                mma_f16_ts(tmem + 128, tmem + 192 + ks * 8, dVh + ks * 2, idesc,
                           (kt == 0 && ks == 0) ? 0u : 1u);
#pragma unroll
            for (int ks = 0; ks < 4; ks++)
                mma_f16_ts(tmem + 128, tmem + 192 + ks * 8, dVl + ks * 2, idesc, 1u);
#pragma unroll
            for (int ks = 0; ks < 4; ks++)
                mma_f16_ts(tmem + 128, tmem + 224 + ks * 8, dVh + ks * 2, idesc, 1u);
            TC_COMMIT(sb + 16);
        }
    }

    MBAR_WAIT(sb + 16, 1);
    TC_FENCE_AFTER();

    *(float*)(smc + FQH + (uint32_t)tid * 4) = lrun;
    __syncthreads();
    const float ltot = lrun + *(const float*)(smc + FQH + (uint32_t)(tid ^ 128) * 4);

    float o[32];
    {
        uint32_t r0[32];
        TC_LD_X32(r0, tmem + 128 + chf * 32);
        TC_WAIT_LD();
#pragma unroll
        for (int j = 0; j < 32; j++) o[j] = __uint_as_float(r0[j]);
    }
    TC_FENCE_BEFORE();

    const float inv = 1.0f / ltot;
    const int qg = q0 + sub * 32 + lane;
    const size_t orow = ((size_t)qg * NB + bb) * DMODEL + (size_t)hh * DKH + chf * 32;
#pragma unroll
    for (int j = 0; j < 32; j += 4) {
        float v0 = o[j] * inv, v1 = o[j + 1] * inv, v2 = o[j + 2] * inv, v3 = o[j + 3] * inv;
        __nv_bfloat16 h0 = __float2bfloat16_rn(v0), h1 = __float2bfloat16_rn(v1);
        __nv_bfloat16 h2 = __float2bfloat16_rn(v2), h3 = __float2bfloat16_rn(v3);
        uint2 uh, ul;
        uh.x = bf2_bits(__nv_bfloat162(h0, h1));
        uh.y = bf2_bits(__nv_bfloat162(h2, h3));
        ul.x = bf2_bits(__nv_bfloat162(
                   __float2bfloat16_rn(v0 - __bfloat162float(h0)),
                   __float2bfloat16_rn(v1 - __bfloat162float(h1))));
        ul.y = bf2_bits(__nv_bfloat162(
                   __float2bfloat16_rn(v2 - __bfloat162float(h2)),
                   __float2bfloat16_rn(v3 - __bfloat162float(h3))));
        *(uint2*)&g_AOh[orow + j] = uh;
        *(uint2*)&g_AOl[orow + j] = ul;
    }
    __syncthreads();
    if (wid == 0) TC_DEALLOC(tmem, 256);

#else  // ---------------- scalar fallback ----------------------------------
    const int tid = threadIdx.x;
    if (tid >= 128) return;
    const int bh  = blockIdx.y;
    const int q0  = blockIdx.x * 128;
    const int bb  = bh >> 4;
    const int hh  = bh & 15;
    const size_t plane = (size_t)bh * PLANE;

    const int qg = q0 + tid;
    float qr[64];
#pragma unroll
    for (int d = 0; d < 64; d++) {
        size_t i = plane + (size_t)qg * 64 + d;
        qr[d] = (__bfloat162float(g_Qh[i]) + __bfloat162float(g_Ql[i])) * 0.125f;
    }

    float o[64];
#pragma unroll
    for (int d = 0; d < 64; d++) o[d] = 0.0f;
    float l = 0.0f;

    for (int kk = 0; kk < S_LEN; kk++) {
        float s = 0.0f;
        for (int d = 0; d < 64; d++) {
            size_t i = plane + (size_t)kk * 64 + d;
            s = fmaf(qr[d], __bfloat162float(g_Kh[i]) + __bfloat162float(g_Kl[i]), s);
        }
        const float pr = __expf(s - 12.0f);
        l += pr;
        for (int d = 0; d < 64; d++) {
            size_t i = plane + (size_t)d * S_LEN + kk;
            o[d] = fmaf(pr, __bfloat162float(g_Vth[i]) + __bfloat162float(g_Vtl[i]), o[d]);
        }
    }
    const float inv = 1.0f / l;
    const size_t orow = ((size_t)qg * NB + bb) * DMODEL + (size_t)hh * DKH;
    for (int d = 0; d < 64; d++) {
        float v = o[d] * inv;
        __nv_bfloat16 hv = __float2bfloat16_rn(v);
        g_AOh[orow + d] = hv;
        g_AOl[orow + d] = __float2bfloat16_rn(v - __bfloat162float(hv));
    }
#endif
}

// ---------------------------------------------------------------------------
extern "C" void kernel_launch(void* const* d_in, const int* in_sizes, int n_in,
                              void* d_out, int out_size)
{
    const float* q  = (const float*)d_in[0];
    const float* k  = (const float*)d_in[1];
    const float* v  = (const float*)d_in[2];
    const float* Wq = (const float*)d_in[3];
    const float* bq = (const float*)d_in[4];
    const float* Wk = (const float*)d_in[5];
    const float* bk = (const float*)d_in[6];
    const float* Wv = (const float*)d_in[7];
    const float* bv = (const float*)d_in[8];
    const float* Wo = (const float*)d_in[9];
    const float* bo = (const float*)d_in[10];
    float* out = (float*)d_out;

    __nv_bfloat16 *qh, *ql, *kh, *kl, *vh, *vl;
    __nv_bfloat16 *wqh, *wql, *wkh, *wkl, *wvh, *wvl, *woh, *wol;
    __nv_bfloat16 *Qh, *Ql, *Kh, *Kl, *Vth, *Vtl, *AOh, *AOl;
    cudaGetSymbolAddress((void**)&qh, g_qh);   cudaGetSymbolAddress((void**)&ql, g_ql);
    cudaGetSymbolAddress((void**)&kh, g_kh);   cudaGetSymbolAddress((void**)&kl, g_kl);
    cudaGetSymbolAddress((void**)&vh, g_vh);   cudaGetSymbolAddress((void**)&vl, g_vl);
    cudaGetSymbolAddress((void**)&wqh, g_wqh); cudaGetSymbolAddress((void**)&wql, g_wql);
    cudaGetSymbolAddress((void**)&wkh, g_wkh); cudaGetSymbolAddress((void**)&wkl, g_wkl);
    cudaGetSymbolAddress((void**)&wvh, g_wvh); cudaGetSymbolAddress((void**)&wvl, g_wvl);
    cudaGetSymbolAddress((void**)&woh, g_woh); cudaGetSymbolAddress((void**)&wol, g_wol);
    cudaGetSymbolAddress((void**)&Qh, g_Qh);   cudaGetSymbolAddress((void**)&Ql, g_Ql);
    cudaGetSymbolAddress((void**)&Kh, g_Kh);   cudaGetSymbolAddress((void**)&Kl, g_Kl);
    cudaGetSymbolAddress((void**)&Vth, g_Vth); cudaGetSymbolAddress((void**)&Vtl, g_Vtl);
    cudaGetSymbolAddress((void**)&AOh, g_AOh); cudaGetSymbolAddress((void**)&AOl, g_AOl);

    cudaFuncSetAttribute(gemm_tc, cudaFuncAttributeMaxDynamicSharedMemorySize, GSMEM);
    cudaFuncSetAttribute(flash_tc, cudaFuncAttributeMaxDynamicSharedMemorySize, FSMEM);

    cvt_all<<<dim3(1024, 7), 256>>>(
        (const float4*)q, (const float4*)k, (const float4*)v,
        (const float4*)Wq, (const float4*)Wk, (const float4*)Wv, (const float4*)Wo,
        (uint2*)qh, (uint2*)kh, (uint2*)vh,
        (uint2*)wqh, (uint2*)wkh, (uint2*)wvh, (uint2*)woh,
        (uint2*)ql, (uint2*)kl, (uint2*)vl,
        (uint2*)wql, (uint2*)wkl, (uint2*)wvl, (uint2*)wol);

    // fused Q/K/V projections: one launch, grid.z selects the problem
    GemmProb3 qkv;
    qkv.p[0] = { qh, ql, wqh, wql, bq, nullptr, Qh,  Ql,  1 };
    qkv.p[1] = { kh, kl, wkh, wkl, bk, nullptr, Kh,  Kl,  1 };
    qkv.p[2] = { vh, vl, wvh, wvl, bv, nullptr, Vth, Vtl, 2 };
    gemm_tc<<<dim3(DMODEL / 128, MROWS / 128, 3), 256, GSMEM>>>(qkv);

    flash_tc<<<dim3(S_LEN / 128, NB * NHEAD), 256, FSMEM>>>();

    GemmProb3 op;
    op.p[0] = { AOh, AOl, woh, wol, bo, out, nullptr, nullptr, 0 };
    op.p[1] = op.p[0];
    op.p[2] = op.p[0];
    gemm_tc<<<dim3(DMODEL / 128, MROWS / 128, 1), 256, GSMEM>>>(op);
}

// round 14
// speedup vs baseline: 1.0482x; 1.0482x over previous
#include <cuda_runtime.h>
#include <cuda_bf16.h>
#include <cstdint>

#define S_LEN   2048
#define NB      2
#define DMODEL  1024
#define NHEAD   16
#define DKH     64
#define MROWS   (S_LEN * NB)   // 4096
#define PLANE   (S_LEN * DKH)  // 131072 elems per (b,h) plane

#if defined(__CUDA_ARCH_FEAT_SM103_ALL) || defined(__CUDA_ARCH_FEAT_SM100_ALL)
#define HAS_TCGEN05 1
#else
#define HAS_TCGEN05 0
#endif

// ---- bf16 hi/lo scratch ----------------------------------------------------
__device__ __nv_bfloat16 g_qh[MROWS * DMODEL], g_ql[MROWS * DMODEL];
__device__ __nv_bfloat16 g_kh[MROWS * DMODEL], g_kl[MROWS * DMODEL];
__device__ __nv_bfloat16 g_vh[MROWS * DMODEL], g_vl[MROWS * DMODEL];
__device__ __nv_bfloat16 g_wqh[DMODEL * DMODEL], g_wql[DMODEL * DMODEL];
__device__ __nv_bfloat16 g_wkh[DMODEL * DMODEL], g_wkl[DMODEL * DMODEL];
__device__ __nv_bfloat16 g_wvh[DMODEL * DMODEL], g_wvl[DMODEL * DMODEL];
__device__ __nv_bfloat16 g_woh[DMODEL * DMODEL], g_wol[DMODEL * DMODEL];
// projections: Q/K planar [bh][s][d], V planar transposed [bh][d][s]
__device__ __nv_bfloat16 g_Qh[32 * PLANE], g_Ql[32 * PLANE];
__device__ __nv_bfloat16 g_Kh[32 * PLANE], g_Kl[32 * PLANE];
__device__ __nv_bfloat16 g_Vth[32 * PLANE], g_Vtl[32 * PLANE];
__device__ __nv_bfloat16 g_AOh[MROWS * DMODEL], g_AOl[MROWS * DMODEL];

// ---------------------------------------------------------------------------
__device__ __forceinline__ uint32_t smem_u32(const void* p) {
    uint32_t a;
    asm("{ .reg .u64 t; cvta.to.shared.u64 t, %1; cvt.u32.u64 %0, t; }"
        : "=r"(a) : "l"(p));
    return a;
}
__device__ __forceinline__ uint32_t elect_one() {
    uint32_t p;
    asm volatile("{ .reg .pred p; elect.sync _|p, 0xFFFFFFFF; selp.b32 %0,1,0,p; }"
                 : "=r"(p));
    return p;
}
__device__ __forceinline__ uint32_t bf2_bits(__nv_bfloat162 v) {
    return *reinterpret_cast<uint32_t*>(&v);
}

#define MBAR_INIT(addr, cnt) \
    asm volatile("mbarrier.init.shared.b64 [%0], %1;" :: "r"(addr), "r"(cnt) : "memory")

#define MBAR_WAIT(addr, parity) do {                                          \
    uint32_t _m = (addr); uint32_t _p = (parity); uint32_t _d;                \
    asm volatile("{ .reg .pred p; mbarrier.try_wait.parity.acquire.cta.shared::cta.b64 p, [%1], %2;" \
                 " selp.b32 %0,1,0,p; }" : "=r"(_d) : "r"(_m), "r"(_p) : "memory"); \
    if (!_d) {                                                                \
        asm volatile("{ .reg .pred P1; WL_%=:"                                \
                     " mbarrier.try_wait.parity.acquire.cta.shared::cta.b64 P1, [%0], %1, 0x989680;" \
                     " @P1 bra.uni WD_%=; bra.uni WL_%=; WD_%=: }"            \
                     :: "r"(_m), "r"(_p) : "memory");                         \
    }                                                                         \
} while (0)

#if HAS_TCGEN05
#define TC_ALLOC(smem_addr, ncols) \
    asm volatile("tcgen05.alloc.cta_group::1.sync.aligned.shared::cta.b32 [%0], %1;" \
                 :: "r"(smem_addr), "r"(ncols) : "memory")
#define TC_RELINQ() \
    asm volatile("tcgen05.relinquish_alloc_permit.cta_group::1.sync.aligned;")
#define TC_DEALLOC(tmem, ncols) \
    asm volatile("tcgen05.dealloc.cta_group::1.sync.aligned.b32 %0, %1;" :: "r"(tmem), "r"(ncols))
#define TC_COMMIT(mbar) \
    asm volatile("tcgen05.commit.cta_group::1.mbarrier::arrive::one.shared::cluster.b64 [%0];" \
                 :: "r"(mbar) : "memory")
#define TC_FENCE_AFTER()   asm volatile("tcgen05.fence::after_thread_sync;" ::: "memory")
#define TC_FENCE_BEFORE()  asm volatile("tcgen05.fence::before_thread_sync;" ::: "memory")
#define TC_WAIT_LD()       asm volatile("tcgen05.wait::ld.sync.aligned;" ::: "memory")
#define TC_WAIT_ST()       asm volatile("tcgen05.wait::st.sync.aligned;" ::: "memory")

#define TC_LD_X32(r, tmem_addr) \
    asm volatile( \
        "tcgen05.ld.sync.aligned.32x32b.x32.b32 " \
        "{%0, %1, %2, %3, %4, %5, %6, %7, %8, %9, %10, %11, %12, %13, %14, %15, " \
        " %16, %17, %18, %19, %20, %21, %22, %23, %24, %25, %26, %27, %28, %29, %30, %31}, [%32];" \
        : "=r"((r)[0]),  "=r"((r)[1]),  "=r"((r)[2]),  "=r"((r)[3]), \
          "=r"((r)[4]),  "=r"((r)[5]),  "=r"((r)[6]),  "=r"((r)[7]), \
          "=r"((r)[8]),  "=r"((r)[9]),  "=r"((r)[10]), "=r"((r)[11]), \
          "=r"((r)[12]), "=r"((r)[13]), "=r"((r)[14]), "=r"((r)[15]), \
          "=r"((r)[16]), "=r"((r)[17]), "=r"((r)[18]), "=r"((r)[19]), \
          "=r"((r)[20]), "=r"((r)[21]), "=r"((r)[22]), "=r"((r)[23]), \
          "=r"((r)[24]), "=r"((r)[25]), "=r"((r)[26]), "=r"((r)[27]), \
          "=r"((r)[28]), "=r"((r)[29]), "=r"((r)[30]), "=r"((r)[31]) \
        : "r"(tmem_addr))

#define TC_ST_X16(tmem_addr, r) \
    asm volatile( \
        "tcgen05.st.sync.aligned.32x32b.x16.b32 [%0], " \
        "{%1, %2, %3, %4, %5, %6, %7, %8, %9, %10, %11, %12, %13, %14, %15, %16};" \
        :: "r"(tmem_addr), \
           "r"((r)[0]),  "r"((r)[1]),  "r"((r)[2]),  "r"((r)[3]), \
           "r"((r)[4]),  "r"((r)[5]),  "r"((r)[6]),  "r"((r)[7]), \
           "r"((r)[8]),  "r"((r)[9]),  "r"((r)[10]), "r"((r)[11]), \
           "r"((r)[12]), "r"((r)[13]), "r"((r)[14]), "r"((r)[15]) \
        : "memory")

__device__ __forceinline__ void mma_f16_ss(uint32_t d_tmem, uint64_t a_desc,
                                           uint64_t b_desc, uint32_t idesc,
                                           uint32_t enable) {
    asm volatile(
        "{ .reg .pred p; setp.ne.u32 p, %4, 0;\n\t"
        "tcgen05.mma.cta_group::1.kind::f16 [%0], %1, %2, %3, {%5,%5,%5,%5}, p;\n\t}"
        :: "r"(d_tmem), "l"(a_desc), "l"(b_desc), "r"(idesc), "r"(enable), "r"(0u)
        : "memory");
}
__device__ __forceinline__ void mma_f16_ts(uint32_t d_tmem, uint32_t a_tmem,
                                           uint64_t b_desc, uint32_t idesc,
                                           uint32_t enable) {
    asm volatile(
        "{ .reg .pred p; setp.ne.u32 p, %4, 0;\n\t"
        "tcgen05.mma.cta_group::1.kind::f16 [%0], [%1], %2, %3, {%5,%5,%5,%5}, p;\n\t}"
        :: "r"(d_tmem), "r"(a_tmem), "l"(b_desc), "r"(idesc), "r"(enable), "r"(0u)
        : "memory");
}
#endif // HAS_TCGEN05

#define SWZ(o)   ((uint32_t)(o) ^ ((((uint32_t)(o)) >> 3) & 0x70u))
#define SWZ64(o) ((uint32_t)(o) ^ ((((uint32_t)(o)) >> 3) & 0x30u))

// SW128 K-major smem descriptor: LBO=1, SBO=64
static __device__ __forceinline__ uint64_t make_desc(uint32_t addr) {
    const uint64_t base = (uint64_t(2) << 61) | (uint64_t(1) << 46) |
                          (uint64_t(64) << 32) | (uint64_t(1) << 16);
    return base | ((uint64_t)(addr >> 4) & 0x3FFFu);
}
// SW64 K-major smem descriptor: layout=4, LBO=1, SBO=32
static __device__ __forceinline__ uint64_t make_desc64(uint32_t addr) {
    const uint64_t base = (uint64_t(4) << 61) | (uint64_t(1) << 46) |
                          (uint64_t(32) << 32) | (uint64_t(1) << 16);
    return base | ((uint64_t)(addr >> 4) & 0x3FFFu);
}

// ---------------------------------------------------------------------------
// Fused fp32 -> bf16 hi/lo split for all 7 tensors (one launch)
// ---------------------------------------------------------------------------
__global__ void __launch_bounds__(256)
cvt_all(const float4* s0, const float4* s1, const float4* s2, const float4* s3,
        const float4* s4, const float4* s5, const float4* s6,
        uint2* h0, uint2* h1, uint2* h2, uint2* h3, uint2* h4, uint2* h5, uint2* h6,
        uint2* l0, uint2* l1, uint2* l2, uint2* l3, uint2* l4, uint2* l5, uint2* l6)
{
    const float4* srcs[7] = { s0, s1, s2, s3, s4, s5, s6 };
    uint2* hs[7] = { h0, h1, h2, h3, h4, h5, h6 };
    uint2* ls[7] = { l0, l1, l2, l3, l4, l5, l6 };
    const int which = blockIdx.y;
    const int n4 = (which < 3) ? (MROWS * DMODEL / 4) : (DMODEL * DMODEL / 4);
    const int base = blockIdx.x * 1024 + threadIdx.x;
    if (base >= n4) return;
    const float4* __restrict__ x = srcs[which];
    uint2* __restrict__ h = hs[which];
    uint2* __restrict__ l = ls[which];
#pragma unroll
    for (int t = 0; t < 4; t++) {
        const int i = base + t * 256;
        if (i >= n4) break;
        float4 f = x[i];
        __nv_bfloat162 hh0 = __floats2bfloat162_rn(f.x, f.y);
        __nv_bfloat162 hh1 = __floats2bfloat162_rn(f.z, f.w);
        float2 hf0 = __bfloat1622float2(hh0), hf1 = __bfloat1622float2(hh1);
        __nv_bfloat162 ll0 = __floats2bfloat162_rn(f.x - hf0.x, f.y - hf0.y);
        __nv_bfloat162 ll1 = __floats2bfloat162_rn(f.z - hf1.x, f.w - hf1.y);
        uint2 hv, lv;
        hv.x = bf2_bits(hh0); hv.y = bf2_bits(hh1);
        lv.x = bf2_bits(ll0); lv.y = bf2_bits(ll1);
        h[i] = hv; l[i] = lv;
    }
}

// ---------------------------------------------------------------------------
// GEMM, K-chunk 32, SW64 tiles, 2 CTAs/SM, one-deep prefetch,
// TRIPLE-buffered smem pipeline (wait targets ch-3: commit round trip hidden).
// smem: ctrl 1K | buf0 32K | buf1 32K | buf2 32K = 99,328 B
// ---------------------------------------------------------------------------
#define GSMEM (1024 + 3 * 32768)

__global__ void __launch_bounds__(256, 2)
gemm_tc(const __nv_bfloat16* __restrict__ Ah, const __nv_bfloat16* __restrict__ Al,
        const __nv_bfloat16* __restrict__ Bh, const __nv_bfloat16* __restrict__ Bl,
        const float* __restrict__ bias, float* __restrict__ out32,
        __nv_bfloat16* __restrict__ outh, __nv_bfloat16* __restrict__ outl, int mode)
{
#if HAS_TCGEN05
    extern __shared__ char smc[];
    const uint32_t sb = smem_u32(smc);
    const int tid = threadIdx.x;
    const int wid = tid >> 5, lid = tid & 31;
    const int m0 = blockIdx.y * 128;
    const int n0 = blockIdx.x * 128;

    if (tid == 0) { MBAR_INIT(sb + 8, 1); MBAR_INIT(sb + 16, 1); MBAR_INIT(sb + 24, 1); }
    if (wid == 0) { TC_ALLOC(sb, 128); TC_RELINQ(); }
    __syncthreads();
    uint32_t tmem;
    asm("ld.shared.b32 %0, [%1];" : "=r"(tmem) : "r"(sb));

    const uint32_t idesc = (1u << 4) | (1u << 7) | (1u << 10) | (16u << 17) | (8u << 24);

    const __nv_bfloat16* srcp[8];
    uint32_t soff[8];
#pragma unroll
    for (int t = 0; t < 8; t++) {
        const int which = t >> 1;
        const int r = (t & 1) * 256 + tid;
        const int row = r >> 2, g = r & 3;
        const __nv_bfloat16* src =
            (which == 0) ? Ah : (which == 1) ? Al : (which == 2) ? Bh : Bl;
        const int base_mn = (which < 2) ? m0 : n0;
        srcp[t] = src + (size_t)(base_mn + row) * DMODEL + g * 8;
        soff[t] = (uint32_t)which * 8192u + SWZ64(row * 64 + g * 16);
    }

    uint4 rg[8];
#pragma unroll
    for (int t = 0; t < 8; t++) rg[t] = *(const uint4*)srcp[t];

    for (int ch = 0; ch < 32; ch++) {
        const int buf = ch % 3;
        const uint32_t tb = 1024u + (uint32_t)buf * 32768u;
        // wait for chunk ch-3's commit on this buffer (3 chains of slack)
        if (ch >= 3) MBAR_WAIT(sb + 8 + buf * 8, (uint32_t)(((ch - 3) / 3) & 1));

#pragma unroll
        for (int t = 0; t < 8; t++)
            *(uint4*)(smc + tb + soff[t]) = rg[t];
        __syncthreads();

        if (ch < 31) {
            const int koff = (ch + 1) * 32;
#pragma unroll
            for (int t = 0; t < 8; t++)
                rg[t] = *(const uint4*)(srcp[t] + koff);
        }

        if (wid == 0 && elect_one()) {
            asm volatile("fence.proxy.async.shared::cta;" ::: "memory");
            const uint64_t dAh = make_desc64(sb + tb);
            const uint64_t dAl = make_desc64(sb + tb + 8192);
            const uint64_t dBh = make_desc64(sb + tb + 16384);
            const uint64_t dBl = make_desc64(sb + tb + 24576);
#pragma unroll
            for (int ks = 0; ks < 2; ks++)
                mma_f16_ss(tmem, dAh + ks * 2, dBh + ks * 2, idesc,
                           (ch == 0 && ks == 0) ? 0u : 1u);
#pragma unroll
            for (int ks = 0; ks < 2; ks++)
                mma_f16_ss(tmem, dAh + ks * 2, dBl + ks * 2, idesc, 1u);
#pragma unroll
            for (int ks = 0; ks < 2; ks++)
                mma_f16_ss(tmem, dAl + ks * 2, dBh + ks * 2, idesc, 1u);
            TC_COMMIT(sb + 8 + buf * 8);
        }
    }

    // final: chunk 31 is the 11th commit on mbar[1] -> parity (11-1)&1 = 0.
    // Its commit covers all prior MMAs (in-order async pipe).
    MBAR_WAIT(sb + 16, 0);
    TC_FENCE_AFTER();

    if (wid < 4) {
        const int m = m0 + wid * 32 + lid;
        const int s = m >> 1, b = m & 1;
#pragma unroll
        for (int c0 = 0; c0 < 128; c0 += 32) {
            uint32_t r[32];
            TC_LD_X32(r, tmem + c0);
            TC_WAIT_LD();
            if (mode == 0) {
#pragma unroll
                for (int j = 0; j < 32; j += 4) {
                    float4 bv = *(const float4*)&bias[n0 + c0 + j];
                    float4 o;
                    o.x = __uint_as_float(r[j + 0]) + bv.x;
                    o.y = __uint_as_float(r[j + 1]) + bv.y;
                    o.z = __uint_as_float(r[j + 2]) + bv.z;
                    o.w = __uint_as_float(r[j + 3]) + bv.w;
                    *(float4*)&out32[(size_t)m * DMODEL + n0 + c0 + j] = o;
                }
            } else {
                const int nb = n0 + c0;
                const int h = nb >> 6, d0 = nb & 63;
                const size_t plane = (size_t)(b * NHEAD + h) * PLANE;
                __nv_bfloat16 vh[32], vl[32];
#pragma unroll
                for (int j = 0; j < 32; j++) {
                    float val = __uint_as_float(r[j]) + bias[nb + j];
                    vh[j] = __float2bfloat16_rn(val);
                    vl[j] = __float2bfloat16_rn(val - __bfloat162float(vh[j]));
                }
                if (mode == 1) {
                    const size_t base = plane + (size_t)s * 64 + d0;
#pragma unroll
                    for (int j = 0; j < 32; j += 4) {
                        uint2 u;
                        u.x = bf2_bits(__nv_bfloat162(vh[j], vh[j + 1]));
                        u.y = bf2_bits(__nv_bfloat162(vh[j + 2], vh[j + 3]));
                        *(uint2*)&outh[base + j] = u;
                        u.x = bf2_bits(__nv_bfloat162(vl[j], vl[j + 1]));
                        u.y = bf2_bits(__nv_bfloat162(vl[j + 2], vl[j + 3]));
                        *(uint2*)&outl[base + j] = u;
                    }
                } else {
                    const size_t base = plane + s;
#pragma unroll
                    for (int j = 0; j < 32; j++) {
                        outh[base + (size_t)(d0 + j) * S_LEN] = vh[j];
                        outl[base + (size_t)(d0 + j) * S_LEN] = vl[j];
                    }
                }
            }
        }
    }
    __syncthreads();
    if (wid == 0) TC_DEALLOC(tmem, 128);

#else  // ---------------- fp32 fallback ------------------------------------
    extern __shared__ char smc[];
    float* As = (float*)smc;
    float* Bs = As + 8 * 128;

    const int tid  = threadIdx.x;
    const int m0   = blockIdx.y * 128;
    const int n0   = blockIdx.x * 128;
    const int tx   = tid & 15;
    const int ty   = tid >> 4;
    const int lrow = tid >> 1;
    const int lc   = (tid & 1) * 4;

    float acc[8][8];
#pragma unroll
    for (int i = 0; i < 8; i++)
#pragma unroll
        for (int j = 0; j < 8; j++) acc[i][j] = 0.0f;

    for (int k0 = 0; k0 < DMODEL; k0 += 8) {
        float av[4], bv[4];
#pragma unroll
        for (int j = 0; j < 4; j++) {
            size_t ai = (size_t)(m0 + lrow) * DMODEL + k0 + lc + j;
            size_t bi = (size_t)(n0 + lrow) * DMODEL + k0 + lc + j;
            av[j] = __bfloat162float(Ah[ai]) + __bfloat162float(Al[ai]);
            bv[j] = __bfloat162float(Bh[bi]) + __bfloat162float(Bl[bi]);
        }
        __syncthreads();
#pragma unroll
        for (int j = 0; j < 4; j++) {
            As[(lc + j) * 128 + lrow] = av[j];
            Bs[(lc + j) * 128 + lrow] = bv[j];
        }
        __syncthreads();
#pragma unroll
        for (int kk = 0; kk < 8; kk++) {
            float a[8], b[8];
            *(float4*)&a[0] = *(const float4*)&As[kk * 128 + ty * 8];
            *(float4*)&a[4] = *(const float4*)&As[kk * 128 + ty * 8 + 4];
            *(float4*)&b[0] = *(const float4*)&Bs[kk * 128 + tx * 8];
            *(float4*)&b[4] = *(const float4*)&Bs[kk * 128 + tx * 8 + 4];
#pragma unroll
            for (int i = 0; i < 8; i++)
#pragma unroll
                for (int j = 0; j < 8; j++)
                    acc[i][j] = fmaf(a[i], b[j], acc[i][j]);
        }
    }

#pragma unroll
    for (int i = 0; i < 8; i++) {
        const int m = m0 + ty * 8 + i;
        const int s = m >> 1, b = m & 1;
#pragma unroll
        for (int j = 0; j < 8; j++) {
            const int n = n0 + tx * 8 + j;
            const float val = acc[i][j] + bias[n];
            if (mode == 0) {
                out32[(size_t)m * DMODEL + n] = val;
            } else {
                const int h = n >> 6, d = n & 63;
                const size_t plane = (size_t)(b * NHEAD + h) * PLANE;
                const size_t idx = (mode == 1) ? plane + (size_t)s * 64 + d
                                               : plane + (size_t)d * S_LEN + s;
                __nv_bfloat16 hv = __float2bfloat16_rn(val);
                outh[idx] = hv;
                outl[idx] = __float2bfloat16_rn(val - __bfloat162float(hv));
            }
        }
    }
#endif
}

// ---------------------------------------------------------------------------
// tcgen05 flash attention (round-11 version, unchanged).
// ---------------------------------------------------------------------------
#define FQH  1024u
#define FQL  17408u
#define FBUF 33792u
#define FSMEM 99328

__global__ void __launch_bounds__(256, 2)
flash_tc()
{
#if HAS_TCGEN05
    extern __shared__ char smc[];
    const uint32_t sb = smem_u32(smc);
    const int tid  = threadIdx.x;
    const int wid  = tid >> 5;
    const int lane = tid & 31;
    const int sub  = wid & 3;
    const int chf  = wid >> 2;
    const int bh   = blockIdx.y;
    const int q0   = blockIdx.x * 128;
    const int bb   = bh >> 4;
    const int hh   = bh & 15;
    const size_t plane = (size_t)bh * PLANE;

    if (tid == 0) { MBAR_INIT(sb + 8, 1); MBAR_INIT(sb + 16, 1); }
    if (wid == 0) { TC_ALLOC(sb, 256); TC_RELINQ(); }
    __syncthreads();
    uint32_t tmem;
    asm("ld.shared.b32 %0, [%1];" : "=r"(tmem) : "r"(sb));

    const uint32_t idesc = (1u << 4) | (1u << 7) | (1u << 10) | (8u << 17) | (8u << 24);
    const uint32_t sub_off = (uint32_t)sub << 21;

#pragma unroll
    for (int t = 0; t < 4; t++) {
        const int idx = t * 256 + tid;
        const int row = idx >> 3, g = idx & 7;
        const size_t off = plane + (size_t)(q0 + row) * 64 + g * 8;
        *(uint4*)(smc + FQH + SWZ(row * 128 + g * 16)) = *(const uint4*)&g_Qh[off];
        *(uint4*)(smc + FQL + SWZ(row * 128 + g * 16)) = *(const uint4*)&g_Ql[off];
    }
#pragma unroll
    for (int t = 0; t < 8; t++) {
        const int idx = t * 256 + tid;
        const int which = idx >> 9;
        const int r = idx & 511;
        const int row = r >> 3, g = r & 7;
        const size_t off = (which < 2) ? plane + (size_t)row * 64 + g * 8
                                       : plane + (size_t)row * S_LEN + g * 8;
        const __nv_bfloat16* src =
            (which == 0) ? g_Kh : (which == 1) ? g_Kl : (which == 2) ? g_Vth : g_Vtl;
        *(uint4*)(smc + FBUF + (uint32_t)which * 8192u + SWZ(row * 128 + g * 16)) =
            *(const uint4*)&src[off];
    }
    __syncthreads();

    const uint64_t dQh = make_desc(sb + FQH);
    const uint64_t dQl = make_desc(sb + FQL);

    if (wid == 0 && elect_one()) {
        asm volatile("fence.proxy.async.shared::cta;" ::: "memory");
        const uint64_t dKh = make_desc(sb + FBUF);
        const uint64_t dKl = make_desc(sb + FBUF + 8192);
#pragma unroll
        for (int ks = 0; ks < 4; ks++)
            mma_f16_ss(tmem, dQh + ks * 2, dKh + ks * 2, idesc, ks == 0 ? 0u : 1u);
#pragma unroll
        for (int ks = 0; ks < 4; ks++)
            mma_f16_ss(tmem, dQh + ks * 2, dKl + ks * 2, idesc, 1u);
#pragma unroll
        for (int ks = 0; ks < 4; ks++)
            mma_f16_ss(tmem, dQl + ks * 2, dKh + ks * 2, idesc, 1u);
        TC_COMMIT(sb + 8);
    }

    float lrun = 0.0f;

    for (int kt = 0; kt < 32; kt++) {
        const int cur = kt & 1;
        const uint32_t bufc = FBUF + (uint32_t)cur * 32768u;
        const uint32_t bufn = FBUF + (uint32_t)(cur ^ 1) * 32768u;
        const uint32_t sS = tmem + (uint32_t)cur * 64u;

        if (kt < 31) {
            const int k0n = (kt + 1) * 64;
#pragma unroll
            for (int t = 0; t < 4; t++) {
                const int idx = t * 256 + tid;
                const int which = idx >> 9;
                const int r = idx & 511;
                const int row = r >> 3, g = r & 7;
                const size_t koff = plane + (size_t)(k0n + row) * 64 + g * 8;
                const __nv_bfloat16* src = which ? g_Kl : g_Kh;
                *(uint4*)(smc + bufn + (uint32_t)which * 8192u + SWZ(row * 128 + g * 16)) =
                    *(const uint4*)&src[koff];
            }
        }

        MBAR_WAIT(sb + 8, kt & 1);
        TC_FENCE_AFTER();
        float p[32];
        {
            uint32_t r0[32];
            TC_LD_X32(r0, sS + chf * 32);
            TC_WAIT_LD();
#pragma unroll
            for (int j = 0; j < 32; j++) p[j] = __uint_as_float(r0[j]);
        }
        TC_FENCE_BEFORE();

        __syncthreads();
        if (kt < 31 && wid == 0 && elect_one()) {
            TC_FENCE_AFTER();
            asm volatile("fence.proxy.async.shared::cta;" ::: "memory");
            const uint64_t dKh = make_desc(sb + bufn);
            const uint64_t dKl = make_desc(sb + bufn + 8192);
            const uint32_t sN = tmem + (uint32_t)(cur ^ 1) * 64u;
#pragma unroll
            for (int ks = 0; ks < 4; ks++)
                mma_f16_ss(sN, dQh + ks * 2, dKh + ks * 2, idesc, ks == 0 ? 0u : 1u);
#pragma unroll
            for (int ks = 0; ks < 4; ks++)
                mma_f16_ss(sN, dQh + ks * 2, dKl + ks * 2, idesc, 1u);
#pragma unroll
            for (int ks = 0; ks < 4; ks++)
                mma_f16_ss(sN, dQl + ks * 2, dKh + ks * 2, idesc, 1u);
            TC_COMMIT(sb + 8);
        }

        float rs = 0.0f;
#pragma unroll
        for (int j = 0; j < 32; j++) {
            p[j] = __expf(fmaf(p[j], 0.125f, -12.0f));
            rs += p[j];
        }
        lrun += rs;

        if (kt > 0) {
            MBAR_WAIT(sb + 16, (kt - 1) & 1);
            TC_FENCE_AFTER();
        }

        if (kt < 31) {
            const int k0n = (kt + 1) * 64;
#pragma unroll
            for (int t = 0; t < 4; t++) {
                const int idx = t * 256 + tid;
                const int which = idx >> 9;
                const int r = idx & 511;
                const int row = r >> 3, g = r & 7;
                const size_t voff = plane + (size_t)row * S_LEN + k0n + g * 8;
                const __nv_bfloat16* src = which ? g_Vtl : g_Vth;
                *(uint4*)(smc + bufn + 16384u + (uint32_t)which * 8192u + SWZ(row * 128 + g * 16)) =
                    *(const uint4*)&src[voff];
            }
        }

        {
            uint32_t ph[16], pl[16];
#pragma unroll
            for (int j = 0; j < 16; j++) {
                __nv_bfloat162 h = __floats2bfloat162_rn(p[2 * j], p[2 * j + 1]);
                float2 hf = __bfloat1622float2(h);
                __nv_bfloat162 l = __floats2bfloat162_rn(p[2 * j] - hf.x, p[2 * j + 1] - hf.y);
                ph[j] = bf2_bits(h);
                pl[j] = bf2_bits(l);
            }
            TC_ST_X16(tmem + 192 + chf * 16 + sub_off, ph);
            TC_ST_X16(tmem + 224 + chf * 16 + sub_off, pl);
            TC_WAIT_ST();
        }
        TC_FENCE_BEFORE();
        __syncthreads();

        if (wid == 0 && elect_one()) {
            TC_FENCE_AFTER();
            asm volatile("fence.proxy.async.shared::cta;" ::: "memory");
            const uint64_t dVh = make_desc(sb + bufc + 16384);
            const uint64_t dVl = make_desc(sb + bufc + 24576);
#pragma unroll
            for (int ks = 0; ks < 4; ks++)
                mma_f16_ts(tmem + 128, tmem + 192 + ks * 8, dVh + ks * 2, idesc,
                           (kt == 0 && ks == 0) ? 0u : 1u);
#pragma unroll
            for (int ks = 0; ks < 4; ks++)
                mma_f16_ts(tmem + 128, tmem + 192 + ks * 8, dVl + ks * 2, idesc, 1u);
#pragma unroll
            for (int ks = 0; ks < 4; ks++)
                mma_f16_ts(tmem + 128, tmem + 224 + ks * 8, dVh + ks * 2, idesc, 1u);
            TC_COMMIT(sb + 16);
        }
    }

    MBAR_WAIT(sb + 16, 1);
    TC_FENCE_AFTER();

    *(float*)(smc + FQH + (uint32_t)tid * 4) = lrun;
    __syncthreads();
    const float ltot = lrun + *(const float*)(smc + FQH + (uint32_t)(tid ^ 128) * 4);

    float o[32];
    {
        uint32_t r0[32];
        TC_LD_X32(r0, tmem + 128 + chf * 32);
        TC_WAIT_LD();
#pragma unroll
        for (int j = 0; j < 32; j++) o[j] = __uint_as_float(r0[j]);
    }
    TC_FENCE_BEFORE();

    const float inv = 1.0f / ltot;
    const int qg = q0 + sub * 32 + lane;
    const size_t orow = ((size_t)qg * NB + bb) * DMODEL + (size_t)hh * DKH + chf * 32;
#pragma unroll
    for (int j = 0; j < 32; j += 4) {
        float v0 = o[j] * inv, v1 = o[j + 1] * inv, v2 = o[j + 2] * inv, v3 = o[j + 3] * inv;
        __nv_bfloat16 h0 = __float2bfloat16_rn(v0), h1 = __float2bfloat16_rn(v1);
        __nv_bfloat16 h2 = __float2bfloat16_rn(v2), h3 = __float2bfloat16_rn(v3);
        uint2 uh, ul;
        uh.x = bf2_bits(__nv_bfloat162(h0, h1));
        uh.y = bf2_bits(__nv_bfloat162(h2, h3));
        ul.x = bf2_bits(__nv_bfloat162(
                   __float2bfloat16_rn(v0 - __bfloat162float(h0)),
                   __float2bfloat16_rn(v1 - __bfloat162float(h1))));
        ul.y = bf2_bits(__nv_bfloat162(
                   __float2bfloat16_rn(v2 - __bfloat162float(h2)),
                   __float2bfloat16_rn(v3 - __bfloat162float(h3))));
        *(uint2*)&g_AOh[orow + j] = uh;
        *(uint2*)&g_AOl[orow + j] = ul;
    }
    __syncthreads();
    if (wid == 0) TC_DEALLOC(tmem, 256);

#else  // ---------------- scalar fallback ----------------------------------
    const int tid = threadIdx.x;
    if (tid >= 128) return;
    const int bh  = blockIdx.y;
    const int q0  = blockIdx.x * 128;
    const int bb  = bh >> 4;
    const int hh  = bh & 15;
    const size_t plane = (size_t)bh * PLANE;

    const int qg = q0 + tid;
    float qr[64];
#pragma unroll
    for (int d = 0; d < 64; d++) {
        size_t i = plane + (size_t)qg * 64 + d;
        qr[d] = (__bfloat162float(g_Qh[i]) + __bfloat162float(g_Ql[i])) * 0.125f;
    }

    float o[64];
#pragma unroll
    for (int d = 0; d < 64; d++) o[d] = 0.0f;
    float l = 0.0f;

    for (int kk = 0; kk < S_LEN; kk++) {
        float s = 0.0f;
        for (int d = 0; d < 64; d++) {
            size_t i = plane + (size_t)kk * 64 + d;
            s = fmaf(qr[d], __bfloat162float(g_Kh[i]) + __bfloat162float(g_Kl[i]), s);
        }
        const float pr = __expf(s - 12.0f);
        l += pr;
        for (int d = 0; d < 64; d++) {
            size_t i = plane + (size_t)d * S_LEN + kk;
            o[d] = fmaf(pr, __bfloat162float(g_Vth[i]) + __bfloat162float(g_Vtl[i]), o[d]);
        }
    }
    const float inv = 1.0f / l;
    const size_t orow = ((size_t)qg * NB + bb) * DMODEL + (size_t)hh * DKH;
    for (int d = 0; d < 64; d++) {
        float v = o[d] * inv;
        __nv_bfloat16 hv = __float2bfloat16_rn(v);
        g_AOh[orow + d] = hv;
        g_AOl[orow + d] = __float2bfloat16_rn(v - __bfloat162float(hv));
    }
#endif
}

// ---------------------------------------------------------------------------
extern "C" void kernel_launch(void* const* d_in, const int* in_sizes, int n_in,
                              void* d_out, int out_size)
{
    const float* q  = (const float*)d_in[0];
    const float* k  = (const float*)d_in[1];
    const float* v  = (const float*)d_in[2];
    const float* Wq = (const float*)d_in[3];
    const float* bq = (const float*)d_in[4];
    const float* Wk = (const float*)d_in[5];
    const float* bk = (const float*)d_in[6];
    const float* Wv = (const float*)d_in[7];
    const float* bv = (const float*)d_in[8];
    const float* Wo = (const float*)d_in[9];
    const float* bo = (const float*)d_in[10];
    float* out = (float*)d_out;

    __nv_bfloat16 *qh, *ql, *kh, *kl, *vh, *vl;
    __nv_bfloat16 *wqh, *wql, *wkh, *wkl, *wvh, *wvl, *woh, *wol;
    __nv_bfloat16 *Qh, *Ql, *Kh, *Kl, *Vth, *Vtl, *AOh, *AOl;
    cudaGetSymbolAddress((void**)&qh, g_qh);   cudaGetSymbolAddress((void**)&ql, g_ql);
    cudaGetSymbolAddress((void**)&kh, g_kh);   cudaGetSymbolAddress((void**)&kl, g_kl);
    cudaGetSymbolAddress((void**)&vh, g_vh);   cudaGetSymbolAddress((void**)&vl, g_vl);
    cudaGetSymbolAddress((void**)&wqh, g_wqh); cudaGetSymbolAddress((void**)&wql, g_wql);
    cudaGetSymbolAddress((void**)&wkh, g_wkh); cudaGetSymbolAddress((void**)&wkl, g_wkl);
    cudaGetSymbolAddress((void**)&wvh, g_wvh); cudaGetSymbolAddress((void**)&wvl, g_wvl);
    cudaGetSymbolAddress((void**)&woh, g_woh); cudaGetSymbolAddress((void**)&wol, g_wol);
    cudaGetSymbolAddress((void**)&Qh, g_Qh);   cudaGetSymbolAddress((void**)&Ql, g_Ql);
    cudaGetSymbolAddress((void**)&Kh, g_Kh);   cudaGetSymbolAddress((void**)&Kl, g_Kl);
    cudaGetSymbolAddress((void**)&Vth, g_Vth); cudaGetSymbolAddress((void**)&Vtl, g_Vtl);
    cudaGetSymbolAddress((void**)&AOh, g_AOh); cudaGetSymbolAddress((void**)&AOl, g_AOl);

    cudaFuncSetAttribute(gemm_tc, cudaFuncAttributeMaxDynamicSharedMemorySize, GSMEM);
    cudaFuncSetAttribute(flash_tc, cudaFuncAttributeMaxDynamicSharedMemorySize, FSMEM);

    cvt_all<<<dim3(1024, 7), 256>>>(
        (const float4*)q, (const float4*)k, (const float4*)v,
        (const float4*)Wq, (const float4*)Wk, (const float4*)Wv, (const float4*)Wo,
        (uint2*)qh, (uint2*)kh, (uint2*)vh,
        (uint2*)wqh, (uint2*)wkh, (uint2*)wvh, (uint2*)woh,
        (uint2*)ql, (uint2*)kl, (uint2*)vl,
        (uint2*)wql, (uint2*)wkl, (uint2*)wvl, (uint2*)wol);

    const dim3 ggrid(DMODEL / 128, MROWS / 128);   // (8, 32)

    gemm_tc<<<ggrid, 256, GSMEM>>>(qh, ql, wqh, wql, bq, nullptr, Qh, Ql, 1);
    gemm_tc<<<ggrid, 256, GSMEM>>>(kh, kl, wkh, wkl, bk, nullptr, Kh, Kl, 1);
    gemm_tc<<<ggrid, 256, GSMEM>>>(vh, vl, wvh, wvl, bv, nullptr, Vth, Vtl, 2);

    flash_tc<<<dim3(S_LEN / 128, NB * NHEAD), 256, FSMEM>>>();

    gemm_tc<<<ggrid, 256, GSMEM>>>(AOh, AOl, woh, wol, bo, out, nullptr, nullptr, 0);
}

// round 16
// speedup vs baseline: 1.1636x; 1.1101x over previous
#include <cuda_runtime.h>
#include <cuda_bf16.h>
#include <cstdint>

#define S_LEN   2048
#define NB      2
#define DMODEL  1024
#define NHEAD   16
#define DKH     64
#define MROWS   (S_LEN * NB)   // 4096
#define PLANE   (S_LEN * DKH)  // 131072 elems per (b,h) plane

#if defined(__CUDA_ARCH_FEAT_SM103_ALL) || defined(__CUDA_ARCH_FEAT_SM100_ALL)
#define HAS_TCGEN05 1
#else
#define HAS_TCGEN05 0
#endif

// ---- bf16 hi/lo scratch ----------------------------------------------------
__device__ __nv_bfloat16 g_qh[MROWS * DMODEL], g_ql[MROWS * DMODEL];
__device__ __nv_bfloat16 g_kh[MROWS * DMODEL], g_kl[MROWS * DMODEL];
__device__ __nv_bfloat16 g_vh[MROWS * DMODEL], g_vl[MROWS * DMODEL];
__device__ __nv_bfloat16 g_wqh[DMODEL * DMODEL], g_wql[DMODEL * DMODEL];
__device__ __nv_bfloat16 g_wkh[DMODEL * DMODEL], g_wkl[DMODEL * DMODEL];
__device__ __nv_bfloat16 g_wvh[DMODEL * DMODEL], g_wvl[DMODEL * DMODEL];
__device__ __nv_bfloat16 g_woh[DMODEL * DMODEL], g_wol[DMODEL * DMODEL];
// projections: Q/K planar [bh][s][d], V planar transposed [bh][d][s]
__device__ __nv_bfloat16 g_Qh[32 * PLANE], g_Ql[32 * PLANE];
__device__ __nv_bfloat16 g_Kh[32 * PLANE], g_Kl[32 * PLANE];
__device__ __nv_bfloat16 g_Vth[32 * PLANE], g_Vtl[32 * PLANE];
__device__ __nv_bfloat16 g_AOh[MROWS * DMODEL], g_AOl[MROWS * DMODEL];

// ---------------------------------------------------------------------------
__device__ __forceinline__ uint32_t smem_u32(const void* p) {
    uint32_t a;
    asm("{ .reg .u64 t; cvta.to.shared.u64 t, %1; cvt.u32.u64 %0, t; }"
        : "=r"(a) : "l"(p));
    return a;
}
__device__ __forceinline__ uint32_t elect_one() {
    uint32_t p;
    asm volatile("{ .reg .pred p; elect.sync _|p, 0xFFFFFFFF; selp.b32 %0,1,0,p; }"
                 : "=r"(p));
    return p;
}
__device__ __forceinline__ uint32_t bf2_bits(__nv_bfloat162 v) {
    return *reinterpret_cast<uint32_t*>(&v);
}

#define MBAR_INIT(addr, cnt) \
    asm volatile("mbarrier.init.shared.b64 [%0], %1;" :: "r"(addr), "r"(cnt) : "memory")

#define MBAR_WAIT(addr, parity) do {                                          \
    uint32_t _m = (addr); uint32_t _p = (parity); uint32_t _d;                \
    asm volatile("{ .reg .pred p; mbarrier.try_wait.parity.acquire.cta.shared::cta.b64 p, [%1], %2;" \
                 " selp.b32 %0,1,0,p; }" : "=r"(_d) : "r"(_m), "r"(_p) : "memory"); \
    if (!_d) {                                                                \
        asm volatile("{ .reg .pred P1; WL_%=:"                                \
                     " mbarrier.try_wait.parity.acquire.cta.shared::cta.b64 P1, [%0], %1, 0x989680;" \
                     " @P1 bra.uni WD_%=; bra.uni WL_%=; WD_%=: }"            \
                     :: "r"(_m), "r"(_p) : "memory");                         \
    }                                                                         \
} while (0)

#if HAS_TCGEN05
#define TC_ALLOC(smem_addr, ncols) \
    asm volatile("tcgen05.alloc.cta_group::1.sync.aligned.shared::cta.b32 [%0], %1;" \
                 :: "r"(smem_addr), "r"(ncols) : "memory")
#define TC_RELINQ() \
    asm volatile("tcgen05.relinquish_alloc_permit.cta_group::1.sync.aligned;")
#define TC_DEALLOC(tmem, ncols) \
    asm volatile("tcgen05.dealloc.cta_group::1.sync.aligned.b32 %0, %1;" :: "r"(tmem), "r"(ncols))
#define TC_COMMIT(mbar) \
    asm volatile("tcgen05.commit.cta_group::1.mbarrier::arrive::one.shared::cluster.b64 [%0];" \
                 :: "r"(mbar) : "memory")
#define TC_FENCE_AFTER()   asm volatile("tcgen05.fence::after_thread_sync;" ::: "memory")
#define TC_FENCE_BEFORE()  asm volatile("tcgen05.fence::before_thread_sync;" ::: "memory")
#define TC_WAIT_LD()       asm volatile("tcgen05.wait::ld.sync.aligned;" ::: "memory")
#define TC_WAIT_ST()       asm volatile("tcgen05.wait::st.sync.aligned;" ::: "memory")

#define TC_LD_X32(r, tmem_addr) \
    asm volatile( \
        "tcgen05.ld.sync.aligned.32x32b.x32.b32 " \
        "{%0, %1, %2, %3, %4, %5, %6, %7, %8, %9, %10, %11, %12, %13, %14, %15, " \
        " %16, %17, %18, %19, %20, %21, %22, %23, %24, %25, %26, %27, %28, %29, %30, %31}, [%32];" \
        : "=r"((r)[0]),  "=r"((r)[1]),  "=r"((r)[2]),  "=r"((r)[3]), \
          "=r"((r)[4]),  "=r"((r)[5]),  "=r"((r)[6]),  "=r"((r)[7]), \
          "=r"((r)[8]),  "=r"((r)[9]),  "=r"((r)[10]), "=r"((r)[11]), \
          "=r"((r)[12]), "=r"((r)[13]), "=r"((r)[14]), "=r"((r)[15]), \
          "=r"((r)[16]), "=r"((r)[17]), "=r"((r)[18]), "=r"((r)[19]), \
          "=r"((r)[20]), "=r"((r)[21]), "=r"((r)[22]), "=r"((r)[23]), \
          "=r"((r)[24]), "=r"((r)[25]), "=r"((r)[26]), "=r"((r)[27]), \
          "=r"((r)[28]), "=r"((r)[29]), "=r"((r)[30]), "=r"((r)[31]) \
        : "r"(tmem_addr))

#define TC_ST_X16(tmem_addr, r) \
    asm volatile( \
        "tcgen05.st.sync.aligned.32x32b.x16.b32 [%0], " \
        "{%1, %2, %3, %4, %5, %6, %7, %8, %9, %10, %11, %12, %13, %14, %15, %16};" \
        :: "r"(tmem_addr), \
           "r"((r)[0]),  "r"((r)[1]),  "r"((r)[2]),  "r"((r)[3]), \
           "r"((r)[4]),  "r"((r)[5]),  "r"((r)[6]),  "r"((r)[7]), \
           "r"((r)[8]),  "r"((r)[9]),  "r"((r)[10]), "r"((r)[11]), \
           "r"((r)[12]), "r"((r)[13]), "r"((r)[14]), "r"((r)[15]) \
        : "memory")

__device__ __forceinline__ void mma_f16_ss(uint32_t d_tmem, uint64_t a_desc,
                                           uint64_t b_desc, uint32_t idesc,
                                           uint32_t enable) {
    asm volatile(
        "{ .reg .pred p; setp.ne.u32 p, %4, 0;\n\t"
        "tcgen05.mma.cta_group::1.kind::f16 [%0], %1, %2, %3, {%5,%5,%5,%5}, p;\n\t}"
        :: "r"(d_tmem), "l"(a_desc), "l"(b_desc), "r"(idesc), "r"(enable), "r"(0u)
        : "memory");
}
__device__ __forceinline__ void mma_f16_ts(uint32_t d_tmem, uint32_t a_tmem,
                                           uint64_t b_desc, uint32_t idesc,
                                           uint32_t enable) {
    asm volatile(
        "{ .reg .pred p; setp.ne.u32 p, %4, 0;\n\t"
        "tcgen05.mma.cta_group::1.kind::f16 [%0], [%1], %2, %3, {%5,%5,%5,%5}, p;\n\t}"
        :: "r"(d_tmem), "r"(a_tmem), "l"(b_desc), "r"(idesc), "r"(enable), "r"(0u)
        : "memory");
}
#endif // HAS_TCGEN05

#define SWZ(o)   ((uint32_t)(o) ^ ((((uint32_t)(o)) >> 3) & 0x70u))
#define SWZ64(o) ((uint32_t)(o) ^ ((((uint32_t)(o)) >> 3) & 0x30u))

#if HAS_TCGEN05
// SW128 K-major smem descriptor: LBO=1, SBO=64
static __device__ __forceinline__ uint64_t make_desc(uint32_t addr) {
    const uint64_t base = (uint64_t(2) << 61) | (uint64_t(1) << 46) |
                          (uint64_t(64) << 32) | (uint64_t(1) << 16);
    return base | ((uint64_t)(addr >> 4) & 0x3FFFu);
}
// SW64 K-major smem descriptor: layout=4, LBO=1, SBO=32
static __device__ __forceinline__ uint64_t make_desc64(uint32_t addr) {
    const uint64_t base = (uint64_t(4) << 61) | (uint64_t(1) << 46) |
                          (uint64_t(32) << 32) | (uint64_t(1) << 16);
    return base | ((uint64_t)(addr >> 4) & 0x3FFFu);
}
#endif

// ---------------------------------------------------------------------------
// Fused fp32 -> bf16 hi/lo split for all 7 tensors (one launch)
// ---------------------------------------------------------------------------
__global__ void __launch_bounds__(256)
cvt_all(const float4* s0, const float4* s1, const float4* s2, const float4* s3,
        const float4* s4, const float4* s5, const float4* s6,
        uint2* h0, uint2* h1, uint2* h2, uint2* h3, uint2* h4, uint2* h5, uint2* h6,
        uint2* l0, uint2* l1, uint2* l2, uint2* l3, uint2* l4, uint2* l5, uint2* l6)
{
    const float4* srcs[7] = { s0, s1, s2, s3, s4, s5, s6 };
    uint2* hs[7] = { h0, h1, h2, h3, h4, h5, h6 };
    uint2* ls[7] = { l0, l1, l2, l3, l4, l5, l6 };
    const int which = blockIdx.y;
    const int n4 = (which < 3) ? (MROWS * DMODEL / 4) : (DMODEL * DMODEL / 4);
    const int base = blockIdx.x * 1024 + threadIdx.x;
    if (base >= n4) return;
    const float4* __restrict__ x = srcs[which];
    uint2* __restrict__ h = hs[which];
    uint2* __restrict__ l = ls[which];
#pragma unroll
    for (int t = 0; t < 4; t++) {
        const int i = base + t * 256;
        if (i >= n4) break;
        float4 f = x[i];
        __nv_bfloat162 hh0 = __floats2bfloat162_rn(f.x, f.y);
        __nv_bfloat162 hh1 = __floats2bfloat162_rn(f.z, f.w);
        float2 hf0 = __bfloat1622float2(hh0), hf1 = __bfloat1622float2(hh1);
        __nv_bfloat162 ll0 = __floats2bfloat162_rn(f.x - hf0.x, f.y - hf0.y);
        __nv_bfloat162 ll1 = __floats2bfloat162_rn(f.z - hf1.x, f.w - hf1.y);
        uint2 hv, lv;
        hv.x = bf2_bits(hh0); hv.y = bf2_bits(hh1);
        lv.x = bf2_bits(ll0); lv.y = bf2_bits(ll1);
        h[i] = hv; l[i] = lv;
    }
}

// ---------------------------------------------------------------------------
// Shared GEMM body (round-11 core, byte-identical schedule).
// mode 0: fp32 row-major; mode 1: planar [bh][s][d]; mode 2: planar [bh][d][s]
// ---------------------------------------------------------------------------
#define GSMEM (1024 + 2 * 32768)

#if HAS_TCGEN05
__device__ __forceinline__ void gemm_body(
        char* smc, uint32_t sb,
        const __nv_bfloat16* __restrict__ Ah, const __nv_bfloat16* __restrict__ Al,
        const __nv_bfloat16* __restrict__ Bh, const __nv_bfloat16* __restrict__ Bl,
        const float* __restrict__ bias, float* __restrict__ out32,
        __nv_bfloat16* __restrict__ outh, __nv_bfloat16* __restrict__ outl, int mode)
{
    const int tid = threadIdx.x;
    const int wid = tid >> 5, lid = tid & 31;
    const int m0 = blockIdx.y * 128;
    const int n0 = blockIdx.x * 128;

    if (tid == 0) { MBAR_INIT(sb + 8, 1); MBAR_INIT(sb + 16, 1); }
    if (wid == 0) { TC_ALLOC(sb, 128); TC_RELINQ(); }
    __syncthreads();
    uint32_t tmem;
    asm("ld.shared.b32 %0, [%1];" : "=r"(tmem) : "r"(sb));

    const uint32_t idesc = (1u << 4) | (1u << 7) | (1u << 10) | (16u << 17) | (8u << 24);

    const __nv_bfloat16* srcp[8];
    uint32_t soff[8];
#pragma unroll
    for (int t = 0; t < 8; t++) {
        const int which = t >> 1;
        const int r = (t & 1) * 256 + tid;
        const int row = r >> 2, g = r & 3;
        const __nv_bfloat16* src =
            (which == 0) ? Ah : (which == 1) ? Al : (which == 2) ? Bh : Bl;
        const int base_mn = (which < 2) ? m0 : n0;
        srcp[t] = src + (size_t)(base_mn + row) * DMODEL + g * 8;
        soff[t] = (uint32_t)which * 8192u + SWZ64(row * 64 + g * 16);
    }

    uint4 rg[8];
#pragma unroll
    for (int t = 0; t < 8; t++) rg[t] = *(const uint4*)srcp[t];

    for (int ch = 0; ch < 32; ch++) {
        const int buf = ch & 1;
        const uint32_t tb = 1024u + (uint32_t)buf * 32768u;
        if (ch >= 2) MBAR_WAIT(sb + 8 + buf * 8, ((ch - 2) >> 1) & 1);

#pragma unroll
        for (int t = 0; t < 8; t++)
            *(uint4*)(smc + tb + soff[t]) = rg[t];
        __syncthreads();

        if (ch < 31) {
            const int koff = (ch + 1) * 32;
#pragma unroll
            for (int t = 0; t < 8; t++)
                rg[t] = *(const uint4*)(srcp[t] + koff);
        }

        if (wid == 0 && elect_one()) {
            asm volatile("fence.proxy.async.shared::cta;" ::: "memory");
            const uint64_t dAh = make_desc64(sb + tb);
            const uint64_t dAl = make_desc64(sb + tb + 8192);
            const uint64_t dBh = make_desc64(sb + tb + 16384);
            const uint64_t dBl = make_desc64(sb + tb + 24576);
#pragma unroll
            for (int ks = 0; ks < 2; ks++)
                mma_f16_ss(tmem, dAh + ks * 2, dBh + ks * 2, idesc,
                           (ch == 0 && ks == 0) ? 0u : 1u);
#pragma unroll
            for (int ks = 0; ks < 2; ks++)
                mma_f16_ss(tmem, dAh + ks * 2, dBl + ks * 2, idesc, 1u);
#pragma unroll
            for (int ks = 0; ks < 2; ks++)
                mma_f16_ss(tmem, dAl + ks * 2, dBh + ks * 2, idesc, 1u);
            TC_COMMIT(sb + 8 + buf * 8);
        }
    }

    MBAR_WAIT(sb + 16, 1);
    TC_FENCE_AFTER();

    if (wid < 4) {
        const int m = m0 + wid * 32 + lid;
        const int s = m >> 1, b = m & 1;
#pragma unroll
        for (int c0 = 0; c0 < 128; c0 += 32) {
            uint32_t r[32];
            TC_LD_X32(r, tmem + c0);
            TC_WAIT_LD();
            if (mode == 0) {
#pragma unroll
                for (int j = 0; j < 32; j += 4) {
                    float4 bv = *(const float4*)&bias[n0 + c0 + j];
                    float4 o;
                    o.x = __uint_as_float(r[j + 0]) + bv.x;
                    o.y = __uint_as_float(r[j + 1]) + bv.y;
                    o.z = __uint_as_float(r[j + 2]) + bv.z;
                    o.w = __uint_as_float(r[j + 3]) + bv.w;
                    *(float4*)&out32[(size_t)m * DMODEL + n0 + c0 + j] = o;
                }
            } else {
                const int nb = n0 + c0;
                const int h = nb >> 6, d0 = nb & 63;
                const size_t plane = (size_t)(b * NHEAD + h) * PLANE;
                __nv_bfloat16 vh[32], vl[32];
#pragma unroll
                for (int j = 0; j < 32; j++) {
                    float val = __uint_as_float(r[j]) + bias[nb + j];
                    vh[j] = __float2bfloat16_rn(val);
                    vl[j] = __float2bfloat16_rn(val - __bfloat162float(vh[j]));
                }
                if (mode == 1) {
                    const size_t base = plane + (size_t)s * 64 + d0;
#pragma unroll
                    for (int j = 0; j < 32; j += 4) {
                        uint2 u;
                        u.x = bf2_bits(__nv_bfloat162(vh[j], vh[j + 1]));
                        u.y = bf2_bits(__nv_bfloat162(vh[j + 2], vh[j + 3]));
                        *(uint2*)&outh[base + j] = u;
                        u.x = bf2_bits(__nv_bfloat162(vl[j], vl[j + 1]));
                        u.y = bf2_bits(__nv_bfloat162(vl[j + 2], vl[j + 3]));
                        *(uint2*)&outl[base + j] = u;
                    }
                } else {
                    const size_t base = plane + s;
#pragma unroll
                    for (int j = 0; j < 32; j++) {
                        outh[base + (size_t)(d0 + j) * S_LEN] = vh[j];
                        outl[base + (size_t)(d0 + j) * S_LEN] = vl[j];
                    }
                }
            }
        }
    }
    __syncthreads();
    if (wid == 0) TC_DEALLOC(tmem, 128);
}
#endif // HAS_TCGEN05

#if !HAS_TCGEN05
// fp32 fallback body (compute_103 PTX pass)
__device__ __forceinline__ void gemm_body_fb(
        char* smc,
        const __nv_bfloat16* Ah, const __nv_bfloat16* Al,
        const __nv_bfloat16* Bh, const __nv_bfloat16* Bl,
        const float* bias, float* out32,
        __nv_bfloat16* outh, __nv_bfloat16* outl, int mode)
{
    float* As = (float*)smc;
    float* Bs = As + 8 * 128;

    const int tid  = threadIdx.x;
    const int m0   = blockIdx.y * 128;
    const int n0   = blockIdx.x * 128;
    const int tx   = tid & 15;
    const int ty   = tid >> 4;
    const int lrow = tid >> 1;
    const int lc   = (tid & 1) * 4;

    float acc[8][8];
#pragma unroll
    for (int i = 0; i < 8; i++)
#pragma unroll
        for (int j = 0; j < 8; j++) acc[i][j] = 0.0f;

    for (int k0 = 0; k0 < DMODEL; k0 += 8) {
        float av[4], bv[4];
#pragma unroll
        for (int j = 0; j < 4; j++) {
            size_t ai = (size_t)(m0 + lrow) * DMODEL + k0 + lc + j;
            size_t bi = (size_t)(n0 + lrow) * DMODEL + k0 + lc + j;
            av[j] = __bfloat162float(Ah[ai]) + __bfloat162float(Al[ai]);
            bv[j] = __bfloat162float(Bh[bi]) + __bfloat162float(Bl[bi]);
        }
        __syncthreads();
#pragma unroll
        for (int j = 0; j < 4; j++) {
            As[(lc + j) * 128 + lrow] = av[j];
            Bs[(lc + j) * 128 + lrow] = bv[j];
        }
        __syncthreads();
#pragma unroll
        for (int kk = 0; kk < 8; kk++) {
            float a[8], b[8];
            *(float4*)&a[0] = *(const float4*)&As[kk * 128 + ty * 8];
            *(float4*)&a[4] = *(const float4*)&As[kk * 128 + ty * 8 + 4];
            *(float4*)&b[0] = *(const float4*)&Bs[kk * 128 + tx * 8];
            *(float4*)&b[4] = *(const float4*)&Bs[kk * 128 + tx * 8 + 4];
#pragma unroll
            for (int i = 0; i < 8; i++)
#pragma unroll
                for (int j = 0; j < 8; j++)
                    acc[i][j] = fmaf(a[i], b[j], acc[i][j]);
        }
    }

#pragma unroll
    for (int i = 0; i < 8; i++) {
        const int m = m0 + ty * 8 + i;
        const int s = m >> 1, b = m & 1;
#pragma unroll
        for (int j = 0; j < 8; j++) {
            const int n = n0 + tx * 8 + j;
            const float val = acc[i][j] + bias[n];
            if (mode == 0) {
                out32[(size_t)m * DMODEL + n] = val;
            } else {
                const int h = n >> 6, d = n & 63;
                const size_t plane = (size_t)(b * NHEAD + h) * PLANE;
                const size_t idx = (mode == 1) ? plane + (size_t)s * 64 + d
                                               : plane + (size_t)d * S_LEN + s;
                __nv_bfloat16 hv = __float2bfloat16_rn(val);
                outh[idx] = hv;
                outl[idx] = __float2bfloat16_rn(val - __bfloat162float(hv));
            }
        }
    }
}
#endif

// QKV projections fused: blockIdx.z selects {Q,K,V}; scratch pointers are the
// static __device__ symbols (immediate addresses), only biases are params.
__global__ void __launch_bounds__(256, 2)
gemm_qkv(const float* __restrict__ bq, const float* __restrict__ bk,
         const float* __restrict__ bv)
{
    const int z = blockIdx.z;
    const __nv_bfloat16* Ah = (z == 0) ? g_qh : (z == 1) ? g_kh : g_vh;
    const __nv_bfloat16* Al = (z == 0) ? g_ql : (z == 1) ? g_kl : g_vl;
    const __nv_bfloat16* Bh = (z == 0) ? g_wqh : (z == 1) ? g_wkh : g_wvh;
    const __nv_bfloat16* Bl = (z == 0) ? g_wql : (z == 1) ? g_wkl : g_wvl;
    const float* bias = (z == 0) ? bq : (z == 1) ? bk : bv;
    __nv_bfloat16* oh = (z == 0) ? g_Qh : (z == 1) ? g_Kh : g_Vth;
    __nv_bfloat16* ol = (z == 0) ? g_Ql : (z == 1) ? g_Kl : g_Vtl;
    const int mode = (z == 2) ? 2 : 1;
#if HAS_TCGEN05
    extern __shared__ char smc[];
    gemm_body(smc, smem_u32(smc), Ah, Al, Bh, Bl, bias, nullptr, oh, ol, mode);
#else
    extern __shared__ char smc[];
    gemm_body_fb(smc, Ah, Al, Bh, Bl, bias, nullptr, oh, ol, mode);
#endif
}

// Output projection (single problem, round-11 launch shape)
__global__ void __launch_bounds__(256, 2)
gemm_tc(const __nv_bfloat16* __restrict__ Ah, const __nv_bfloat16* __restrict__ Al,
        const __nv_bfloat16* __restrict__ Bh, const __nv_bfloat16* __restrict__ Bl,
        const float* __restrict__ bias, float* __restrict__ out32)
{
#if HAS_TCGEN05
    extern __shared__ char smc[];
    gemm_body(smc, smem_u32(smc), Ah, Al, Bh, Bl, bias, out32, nullptr, nullptr, 0);
#else
    extern __shared__ char smc[];
    gemm_body_fb(smc, Ah, Al, Bh, Bl, bias, out32, nullptr, nullptr, 0);
#endif
}

// ---------------------------------------------------------------------------
// tcgen05 flash attention (round-11 version; exp2 constant fold only).
// ---------------------------------------------------------------------------
#define FQH  1024u
#define FQL  17408u
#define FBUF 33792u
#define FSMEM 99328

__global__ void __launch_bounds__(256, 2)
flash_tc()
{
#if HAS_TCGEN05
    extern __shared__ char smc[];
    const uint32_t sb = smem_u32(smc);
    const int tid  = threadIdx.x;
    const int wid  = tid >> 5;
    const int lane = tid & 31;
    const int sub  = wid & 3;
    const int chf  = wid >> 2;
    const int bh   = blockIdx.y;
    const int q0   = blockIdx.x * 128;
    const int bb   = bh >> 4;
    const int hh   = bh & 15;
    const size_t plane = (size_t)bh * PLANE;

    if (tid == 0) { MBAR_INIT(sb + 8, 1); MBAR_INIT(sb + 16, 1); }
    if (wid == 0) { TC_ALLOC(sb, 256); TC_RELINQ(); }
    __syncthreads();
    uint32_t tmem;
    asm("ld.shared.b32 %0, [%1];" : "=r"(tmem) : "r"(sb));

    const uint32_t idesc = (1u << 4) | (1u << 7) | (1u << 10) | (8u << 17) | (8u << 24);
    const uint32_t sub_off = (uint32_t)sub << 21;

#pragma unroll
    for (int t = 0; t < 4; t++) {
        const int idx = t * 256 + tid;
        const int row = idx >> 3, g = idx & 7;
        const size_t off = plane + (size_t)(q0 + row) * 64 + g * 8;
        *(uint4*)(smc + FQH + SWZ(row * 128 + g * 16)) = *(const uint4*)&g_Qh[off];
        *(uint4*)(smc + FQL + SWZ(row * 128 + g * 16)) = *(const uint4*)&g_Ql[off];
    }
#pragma unroll
    for (int t = 0; t < 8; t++) {
        const int idx = t * 256 + tid;
        const int which = idx >> 9;
        const int r = idx & 511;
        const int row = r >> 3, g = r & 7;
        const size_t off = (which < 2) ? plane + (size_t)row * 64 + g * 8
                                       : plane + (size_t)row * S_LEN + g * 8;
        const __nv_bfloat16* src =
            (which == 0) ? g_Kh : (which == 1) ? g_Kl : (which == 2) ? g_Vth : g_Vtl;
        *(uint4*)(smc + FBUF + (uint32_t)which * 8192u + SWZ(row * 128 + g * 16)) =
            *(const uint4*)&src[off];
    }
    __syncthreads();

    const uint64_t dQh = make_desc(sb + FQH);
    const uint64_t dQl = make_desc(sb + FQL);

    if (wid == 0 && elect_one()) {
        asm volatile("fence.proxy.async.shared::cta;" ::: "memory");
        const uint64_t dKh = make_desc(sb + FBUF);
        const uint64_t dKl = make_desc(sb + FBUF + 8192);
#pragma unroll
        for (int ks = 0; ks < 4; ks++)
            mma_f16_ss(tmem, dQh + ks * 2, dKh + ks * 2, idesc, ks == 0 ? 0u : 1u);
#pragma unroll
        for (int ks = 0; ks < 4; ks++)
            mma_f16_ss(tmem, dQh + ks * 2, dKl + ks * 2, idesc, 1u);
#pragma unroll
        for (int ks = 0; ks < 4; ks++)
            mma_f16_ss(tmem, dQl + ks * 2, dKh + ks * 2, idesc, 1u);
        TC_COMMIT(sb + 8);
    }

    float lrun = 0.0f;
    const float C1 = 0.125f * 1.4426950408889634f;    // log2(e)/8
    const float C2 = -12.0f * 1.4426950408889634f;

    for (int kt = 0; kt < 32; kt++) {
        const int cur = kt & 1;
        const uint32_t bufc = FBUF + (uint32_t)cur * 32768u;
        const uint32_t bufn = FBUF + (uint32_t)(cur ^ 1) * 32768u;
        const uint32_t sS = tmem + (uint32_t)cur * 64u;

        if (kt < 31) {
            const int k0n = (kt + 1) * 64;
#pragma unroll
            for (int t = 0; t < 4; t++) {
                const int idx = t * 256 + tid;
                const int which = idx >> 9;
                const int r = idx & 511;
                const int row = r >> 3, g = r & 7;
                const size_t koff = plane + (size_t)(k0n + row) * 64 + g * 8;
                const __nv_bfloat16* src = which ? g_Kl : g_Kh;
                *(uint4*)(smc + bufn + (uint32_t)which * 8192u + SWZ(row * 128 + g * 16)) =
                    *(const uint4*)&src[koff];
            }
        }

        MBAR_WAIT(sb + 8, kt & 1);
        TC_FENCE_AFTER();
        float p[32];
        {
            uint32_t r0[32];
            TC_LD_X32(r0, sS + chf * 32);
            TC_WAIT_LD();
#pragma unroll
            for (int j = 0; j < 32; j++) p[j] = __uint_as_float(r0[j]);
        }
        TC_FENCE_BEFORE();

        __syncthreads();
        if (kt < 31 && wid == 0 && elect_one()) {
            TC_FENCE_AFTER();
            asm volatile("fence.proxy.async.shared::cta;" ::: "memory");
            const uint64_t dKh = make_desc(sb + bufn);
            const uint64_t dKl = make_desc(sb + bufn + 8192);
            const uint32_t sN = tmem + (uint32_t)(cur ^ 1) * 64u;
#pragma unroll
            for (int ks = 0; ks < 4; ks++)
                mma_f16_ss(sN, dQh + ks * 2, dKh + ks * 2, idesc, ks == 0 ? 0u : 1u);
#pragma unroll
            for (int ks = 0; ks < 4; ks++)
                mma_f16_ss(sN, dQh + ks * 2, dKl + ks * 2, idesc, 1u);
#pragma unroll
            for (int ks = 0; ks < 4; ks++)
                mma_f16_ss(sN, dQl + ks * 2, dKh + ks * 2, idesc, 1u);
            TC_COMMIT(sb + 8);
        }

        float rs = 0.0f;
#pragma unroll
        for (int j = 0; j < 32; j++) {
            p[j] = exp2f(fmaf(p[j], C1, C2));
            rs += p[j];
        }
        lrun += rs;

        if (kt > 0) {
            MBAR_WAIT(sb + 16, (kt - 1) & 1);
            TC_FENCE_AFTER();
        }

        if (kt < 31) {
            const int k0n = (kt + 1) * 64;
#pragma unroll
            for (int t = 0; t < 4; t++) {
                const int idx = t * 256 + tid;
                const int which = idx >> 9;
                const int r = idx & 511;
                const int row = r >> 3, g = r & 7;
                const size_t voff = plane + (size_t)row * S_LEN + k0n + g * 8;
                const __nv_bfloat16* src = which ? g_Vtl : g_Vth;
                *(uint4*)(smc + bufn + 16384u + (uint32_t)which * 8192u + SWZ(row * 128 + g * 16)) =
                    *(const uint4*)&src[voff];
            }
        }

        {
            uint32_t ph[16], pl[16];
#pragma unroll
            for (int j = 0; j < 16; j++) {
                __nv_bfloat162 h = __floats2bfloat162_rn(p[2 * j], p[2 * j + 1]);
                float2 hf = __bfloat1622float2(h);
                __nv_bfloat162 l = __floats2bfloat162_rn(p[2 * j] - hf.x, p[2 * j + 1] - hf.y);
                ph[j] = bf2_bits(h);
                pl[j] = bf2_bits(l);
            }
            TC_ST_X16(tmem + 192 + chf * 16 + sub_off, ph);
            TC_ST_X16(tmem + 224 + chf * 16 + sub_off, pl);
            TC_WAIT_ST();
        }
        TC_FENCE_BEFORE();
        __syncthreads();

        if (wid == 0 && elect_one()) {
            TC_FENCE_AFTER();
            asm volatile("fence.proxy.async.shared::cta;" ::: "memory");
            const uint64_t dVh = make_desc(sb + bufc + 16384);
            const uint64_t dVl = make_desc(sb + bufc + 24576);
#pragma unroll
            for (int ks = 0; ks < 4; ks++)
                mma_f16_ts(tmem + 128, tmem + 192 + ks * 8, dVh + ks * 2, idesc,
                           (kt == 0 && ks == 0) ? 0u : 1u);
#pragma unroll
            for (int ks = 0; ks < 4; ks++)
                mma_f16_ts(tmem + 128, tmem + 192 + ks * 8, dVl + ks * 2, idesc, 1u);
#pragma unroll
            for (int ks = 0; ks < 4; ks++)
                mma_f16_ts(tmem + 128, tmem + 224 + ks * 8, dVh + ks * 2, idesc, 1u);
            TC_COMMIT(sb + 16);
        }
    }

    MBAR_WAIT(sb + 16, 1);
    TC_FENCE_AFTER();

    *(float*)(smc + FQH + (uint32_t)tid * 4) = lrun;
    __syncthreads();
    const float ltot = lrun + *(const float*)(smc + FQH + (uint32_t)(tid ^ 128) * 4);

    float o[32];
    {
        uint32_t r0[32];
        TC_LD_X32(r0, tmem + 128 + chf * 32);
        TC_WAIT_LD();
#pragma unroll
        for (int j = 0; j < 32; j++) o[j] = __uint_as_float(r0[j]);
    }
    TC_FENCE_BEFORE();

    const float inv = 1.0f / ltot;
    const int qg = q0 + sub * 32 + lane;
    const size_t orow = ((size_t)qg * NB + bb) * DMODEL + (size_t)hh * DKH + chf * 32;
#pragma unroll
    for (int j = 0; j < 32; j += 4) {
        float v0 = o[j] * inv, v1 = o[j + 1] * inv, v2 = o[j + 2] * inv, v3 = o[j + 3] * inv;
        __nv_bfloat16 h0 = __float2bfloat16_rn(v0), h1 = __float2bfloat16_rn(v1);
        __nv_bfloat16 h2 = __float2bfloat16_rn(v2), h3 = __float2bfloat16_rn(v3);
        uint2 uh, ul;
        uh.x = bf2_bits(__nv_bfloat162(h0, h1));
        uh.y = bf2_bits(__nv_bfloat162(h2, h3));
        ul.x = bf2_bits(__nv_bfloat162(
                   __float2bfloat16_rn(v0 - __bfloat162float(h0)),
                   __float2bfloat16_rn(v1 - __bfloat162float(h1))));
        ul.y = bf2_bits(__nv_bfloat162(
                   __float2bfloat16_rn(v2 - __bfloat162float(h2)),
                   __float2bfloat16_rn(v3 - __bfloat162float(h3))));
        *(uint2*)&g_AOh[orow + j] = uh;
        *(uint2*)&g_AOl[orow + j] = ul;
    }
    __syncthreads();
    if (wid == 0) TC_DEALLOC(tmem, 256);

#else  // ---------------- scalar fallback ----------------------------------
    const int tid = threadIdx.x;
    if (tid >= 128) return;
    const int bh  = blockIdx.y;
    const int q0  = blockIdx.x * 128;
    const int bb  = bh >> 4;
    const int hh  = bh & 15;
    const size_t plane = (size_t)bh * PLANE;

    const int qg = q0 + tid;
    float qr[64];
#pragma unroll
    for (int d = 0; d < 64; d++) {
        size_t i = plane + (size_t)qg * 64 + d;
        qr[d] = (__bfloat162float(g_Qh[i]) + __bfloat162float(g_Ql[i])) * 0.125f;
    }

    float o[64];
#pragma unroll
    for (int d = 0; d < 64; d++) o[d] = 0.0f;
    float l = 0.0f;

    for (int kk = 0; kk < S_LEN; kk++) {
        float s = 0.0f;
        for (int d = 0; d < 64; d++) {
            size_t i = plane + (size_t)kk * 64 + d;
            s = fmaf(qr[d], __bfloat162float(g_Kh[i]) + __bfloat162float(g_Kl[i]), s);
        }
        const float pr = __expf(s - 12.0f);
        l += pr;
        for (int d = 0; d < 64; d++) {
            size_t i = plane + (size_t)d * S_LEN + kk;
            o[d] = fmaf(pr, __bfloat162float(g_Vth[i]) + __bfloat162float(g_Vtl[i]), o[d]);
        }
    }
    const float inv = 1.0f / l;
    const size_t orow = ((size_t)qg * NB + bb) * DMODEL + (size_t)hh * DKH;
    for (int d = 0; d < 64; d++) {
        float v = o[d] * inv;
        __nv_bfloat16 hv = __float2bfloat16_rn(v);
        g_AOh[orow + d] = hv;
        g_AOl[orow + d] = __float2bfloat16_rn(v - __bfloat162float(hv));
    }
#endif
}

// ---------------------------------------------------------------------------
extern "C" void kernel_launch(void* const* d_in, const int* in_sizes, int n_in,
                              void* d_out, int out_size)
{
    const float* q  = (const float*)d_in[0];
    const float* k  = (const float*)d_in[1];
    const float* v  = (const float*)d_in[2];
    const float* Wq = (const float*)d_in[3];
    const float* bq = (const float*)d_in[4];
    const float* Wk = (const float*)d_in[5];
    const float* bk = (const float*)d_in[6];
    const float* Wv = (const float*)d_in[7];
    const float* bv = (const float*)d_in[8];
    const float* Wo = (const float*)d_in[9];
    const float* bo = (const float*)d_in[10];
    float* out = (float*)d_out;

    __nv_bfloat16 *qh, *ql, *kh, *kl, *vh, *vl;
    __nv_bfloat16 *wqh, *wql, *wkh, *wkl, *wvh, *wvl, *woh, *wol;
    __nv_bfloat16 *AOh, *AOl;
    cudaGetSymbolAddress((void**)&qh, g_qh);   cudaGetSymbolAddress((void**)&ql, g_ql);
    cudaGetSymbolAddress((void**)&kh, g_kh);   cudaGetSymbolAddress((void**)&kl, g_kl);
    cudaGetSymbolAddress((void**)&vh, g_vh);   cudaGetSymbolAddress((void**)&vl, g_vl);
    cudaGetSymbolAddress((void**)&wqh, g_wqh); cudaGetSymbolAddress((void**)&wql, g_wql);
    cudaGetSymbolAddress((void**)&wkh, g_wkh); cudaGetSymbolAddress((void**)&wkl, g_wkl);
    cudaGetSymbolAddress((void**)&wvh, g_wvh); cudaGetSymbolAddress((void**)&wvl, g_wvl);
    cudaGetSymbolAddress((void**)&woh, g_woh); cudaGetSymbolAddress((void**)&wol, g_wol);
    cudaGetSymbolAddress((void**)&AOh, g_AOh); cudaGetSymbolAddress((void**)&AOl, g_AOl);

    cudaFuncSetAttribute(gemm_qkv, cudaFuncAttributeMaxDynamicSharedMemorySize, GSMEM);
    cudaFuncSetAttribute(gemm_tc, cudaFuncAttributeMaxDynamicSharedMemorySize, GSMEM);
    cudaFuncSetAttribute(flash_tc, cudaFuncAttributeMaxDynamicSharedMemorySize, FSMEM);

    cvt_all<<<dim3(1024, 7), 256>>>(
        (const float4*)q, (const float4*)k, (const float4*)v,
        (const float4*)Wq, (const float4*)Wk, (const float4*)Wv, (const float4*)Wo,
        (uint2*)qh, (uint2*)kh, (uint2*)vh,
        (uint2*)wqh, (uint2*)wkh, (uint2*)wvh, (uint2*)woh,
        (uint2*)ql, (uint2*)kl, (uint2*)vl,
        (uint2*)wql, (uint2*)wkl, (uint2*)wvl, (uint2*)wol);

    // fused QKV projections: 768 CTAs, full 2-CTA/SM residency through 2.6 waves
    gemm_qkv<<<dim3(DMODEL / 128, MROWS / 128, 3), 256, GSMEM>>>(bq, bk, bv);

    flash_tc<<<dim3(S_LEN / 128, NB * NHEAD), 256, FSMEM>>>();

    gemm_tc<<<dim3(DMODEL / 128, MROWS / 128), 256, GSMEM>>>(
        AOh, AOl, woh, wol, bo, out);
}